// round 15
// baseline (speedup 1.0000x reference)
#include <cuda_runtime.h>
#include <cuda_bf16.h>
#include <mma.h>
#include <math.h>
#include <stdint.h>

using namespace nvcuda;

// ---------------------------------------------------------------------------
// Problem constants
// ---------------------------------------------------------------------------
#define BB   16
#define CIN  32
#define COUT 64
#define NNODE 1024
#define TT   24
#define NT   (NNODE*TT)        // 24576
#define SDIM 16
#define EB   (SDIM*BB*TT)      // 6144  cols of Ubig / Z
#define JCOLS (BB*COUT*TT)     // 24576 cols of XSp / Y1p / Y2r
#define BIG  (BB*COUT*NT)      // 25165824

// packed transposed-weight scratch offsets (floats)
#define WT_DQ1 0
#define WT_KVT 8192
#define WT_C1  16384
#define WT_QS  32768
#define WT_KVS 36864
#define WT_G   45056

// ---------------------------------------------------------------------------
// Scratch (static device globals -- no allocation allowed)
// ---------------------------------------------------------------------------
__device__ __align__(16) float g_delay[NT];
__device__ __align__(16) float g_M[NNODE*COUT];
__device__ __align__(16) float g_rowsum[NNODE];
__device__ __align__(16) float g_u[BB*NT];
__device__ __align__(16) float g_Z[NNODE*EB];
__device__ __align__(16) float g_xin1[BIG];
__device__ __align__(16) float g_XSp[(size_t)NNODE*JCOLS];
__device__ __align__(16) float g_Y1p[(size_t)NNODE*JCOLS];
__device__ __align__(16) float g_Y2r[(size_t)NNODE*JCOLS];
__device__ __align__(16) float g_WT[69632];
// bf16 split operands for the tensor-core GEMMs
__device__ __align__(16) __nv_bfloat16 g_Ah[NNODE*NNODE];
__device__ __align__(16) __nv_bfloat16 g_Al[NNODE*NNODE];
__device__ __align__(16) __nv_bfloat16 g_Bh[(size_t)NNODE*JCOLS];
__device__ __align__(16) __nv_bfloat16 g_Bl[(size_t)NNODE*JCOLS];
__device__ __align__(16) __nv_bfloat16 g_Ch[(size_t)NNODE*JCOLS];
__device__ __align__(16) __nv_bfloat16 g_Cl[(size_t)NNODE*JCOLS];

__device__ __forceinline__ float sigmoidf_(float z) {
    return 1.f / (1.f + __expf(-z));
}
__device__ __forceinline__ void bf16split(float v, __nv_bfloat16& h, __nv_bfloat16& l) {
    h = __float2bfloat16(v);
    l = __float2bfloat16(v - __bfloat162float(h));
}

__device__ __forceinline__ uint32_t smem_u32(const void* p) {
    uint32_t a;
    asm("{ .reg .u64 t; cvta.to.shared.u64 t, %1; cvt.u32.u64 %0, t; }" : "=r"(a) : "l"(p));
    return a;
}
#define CP_ASYNC16(dst, src) \
    asm volatile("cp.async.ca.shared.global [%0], [%1], 16;" :: "r"(dst), "l"(src))
#define CP_COMMIT() asm volatile("cp.async.commit_group;" ::: "memory")
#define CP_WAIT1()  asm volatile("cp.async.wait_group 1;" ::: "memory")
#define CP_WAIT0()  asm volatile("cp.async.wait_group 0;" ::: "memory")

// ---------------------------------------------------------------------------
// split fp32 matrix -> bf16 hi/lo (vectorized by 4) -- used for adj/supports
// ---------------------------------------------------------------------------
__global__ void split_mat(const float* __restrict__ src, __nv_bfloat16* __restrict__ hi,
                          __nv_bfloat16* __restrict__ lo, int n4) {
    int i = blockIdx.x * 256 + threadIdx.x;
    if (i >= n4) return;
    float4 v = ((const float4*)src)[i];
    __nv_bfloat16 h0, h1, h2, h3, l0, l1, l2, l3;
    bf16split(v.x, h0, l0); bf16split(v.y, h1, l1);
    bf16split(v.z, h2, l2); bf16split(v.w, h3, l3);
    uint2 ph, pl;
    ph.x = (uint32_t)__bfloat16_as_ushort(h0) | ((uint32_t)__bfloat16_as_ushort(h1) << 16);
    ph.y = (uint32_t)__bfloat16_as_ushort(h2) | ((uint32_t)__bfloat16_as_ushort(h3) << 16);
    pl.x = (uint32_t)__bfloat16_as_ushort(l0) | ((uint32_t)__bfloat16_as_ushort(l1) << 16);
    pl.y = (uint32_t)__bfloat16_as_ushort(l2) | ((uint32_t)__bfloat16_as_ushort(l3) << 16);
    *(uint2*)&hi[(size_t)i * 4] = ph;
    *(uint2*)&lo[(size_t)i * 4] = pl;
}

// ---------------------------------------------------------------------------
// wmma bf16 split-precision GEMM, cp.async double-buffered, 64x64 warp tiles:
//   C(1024 x Nc) = alpha * A(1024x1024) @ B(1024xNc)
//   C = Ah*Bh + Ah*Bl + Al*Bh accumulated in fp32.
// CTA tile 256(m) x 128(n), 8 warps in 4x2 grid, each warp 64x64 (4x4 accs).
// If Chi != nullptr, also writes bf16 hi/lo split of C (fused split epilogue).
//
// Dynamic smem layout (halves):
//   sAh [2][256][40]  @ 0       (20480)
//   sAl [2][256][40]  @ 20480   (20480)
//   sBh [2][32][136]  @ 40960   ( 8704)
//   sBl [2][32][136]  @ 49664   ( 8704)
//   total 58368 halves = 116736 bytes
// ---------------------------------------------------------------------------
#define GW_SMEM 116736

__global__ void __launch_bounds__(256)
gemm_wmma(const __nv_bfloat16* __restrict__ Ah, const __nv_bfloat16* __restrict__ Al,
          const __nv_bfloat16* __restrict__ Bh, const __nv_bfloat16* __restrict__ Bl,
          float* __restrict__ C, __nv_bfloat16* __restrict__ Chi,
          __nv_bfloat16* __restrict__ Clo, int Nc, float alpha) {
    extern __shared__ __align__(16) __nv_bfloat16 sm[];
    __nv_bfloat16* sAh = sm;
    __nv_bfloat16* sAl = sm + 20480;
    __nv_bfloat16* sBh = sm + 40960;
    __nv_bfloat16* sBl = sm + 49664;
    uint32_t uAh = smem_u32(sAh), uAl = smem_u32(sAl);
    uint32_t uBh = smem_u32(sBh), uBl = smem_u32(sBl);

    int tid = threadIdx.x;
    int wid = tid >> 5, lane = tid & 31;
    int bm = blockIdx.y * 256, bn = blockIdx.x * 128;
    int wm = (wid >> 1) * 64;   // 0,64,128,192
    int wn = (wid & 1) * 64;    // 0,64

    wmma::fragment<wmma::accumulator, 16, 16, 16, float> acc[4][4];
#pragma unroll
    for (int i = 0; i < 4; i++)
#pragma unroll
        for (int j = 0; j < 4; j++) wmma::fill_fragment(acc[i][j], 0.f);

    // A staging: 256x32 halves = 16KB per array = 1024 x 16B chunks; 4/thread
    // chunk p: row = p>>2, col halves = (p&3)*8
    // B staging: 32x128 halves = 8KB per array = 512 chunks; 2/thread
    // chunk p: row = p>>4, col halves = (p&15)*8
#define ISSUE(ch, s) do {                                                              \
    int _k0 = (ch) * 32;                                                               \
    _Pragma("unroll")                                                                  \
    for (int _q = 0; _q < 4; _q++) {                                                   \
        int _p = tid + _q * 256;                                                       \
        int _r = _p >> 2, _c = (_p & 3) << 3;                                          \
        const __nv_bfloat16* _gh = Ah + (size_t)(bm + _r) * 1024 + _k0 + _c;           \
        const __nv_bfloat16* _gl = Al + (size_t)(bm + _r) * 1024 + _k0 + _c;           \
        uint32_t _d = (((s) * 256 + _r) * 40 + _c) * 2;                                \
        CP_ASYNC16(uAh + _d, _gh);                                                     \
        CP_ASYNC16(uAl + _d, _gl);                                                     \
    }                                                                                  \
    _Pragma("unroll")                                                                  \
    for (int _q = 0; _q < 2; _q++) {                                                   \
        int _p = tid + _q * 256;                                                       \
        int _r = _p >> 4, _c = (_p & 15) << 3;                                         \
        const __nv_bfloat16* _gh = Bh + (size_t)(_k0 + _r) * Nc + bn + _c;             \
        const __nv_bfloat16* _gl = Bl + (size_t)(_k0 + _r) * Nc + bn + _c;             \
        uint32_t _d = (((s) * 32 + _r) * 136 + _c) * 2;                                \
        CP_ASYNC16(uBh + _d, _gh);                                                     \
        CP_ASYNC16(uBl + _d, _gl);                                                     \
    }                                                                                  \
} while (0)

    ISSUE(0, 0);
    CP_COMMIT();

    for (int ch = 0; ch < 32; ch++) {
        int s = ch & 1;
        if (ch + 1 < 32) {
            ISSUE(ch + 1, (ch + 1) & 1);
            CP_COMMIT();
            CP_WAIT1();
        } else {
            CP_WAIT0();
        }
        __syncthreads();

#pragma unroll
        for (int kk = 0; kk < 32; kk += 16) {
            wmma::fragment<wmma::matrix_a, 16, 16, 16, __nv_bfloat16, wmma::row_major> fah[4], fal[4];
#pragma unroll
            for (int i = 0; i < 4; i++) {
                wmma::load_matrix_sync(fah[i], &sAh[(s * 256 + wm + i * 16) * 40 + kk], 40);
                wmma::load_matrix_sync(fal[i], &sAl[(s * 256 + wm + i * 16) * 40 + kk], 40);
            }
#pragma unroll
            for (int j = 0; j < 4; j++) {
                wmma::fragment<wmma::matrix_b, 16, 16, 16, __nv_bfloat16, wmma::row_major> fbh, fbl;
                wmma::load_matrix_sync(fbh, &sBh[(s * 32 + kk) * 136 + wn + j * 16], 136);
                wmma::load_matrix_sync(fbl, &sBl[(s * 32 + kk) * 136 + wn + j * 16], 136);
#pragma unroll
                for (int i = 0; i < 4; i++) {
                    wmma::mma_sync(acc[i][j], fah[i], fbh, acc[i][j]);
                    wmma::mma_sync(acc[i][j], fah[i], fbl, acc[i][j]);
                    wmma::mma_sync(acc[i][j], fal[i], fbh, acc[i][j]);
                }
            }
        }
        __syncthreads();
    }
#undef ISSUE

    if (Chi == nullptr) {
#pragma unroll
        for (int i = 0; i < 4; i++)
#pragma unroll
            for (int j = 0; j < 4; j++) {
#pragma unroll
                for (int e = 0; e < 8; e++) acc[i][j].x[e] *= alpha;
                wmma::store_matrix_sync(&C[(size_t)(bm + wm + i * 16) * Nc + bn + wn + j * 16],
                                        acc[i][j], Nc, wmma::mem_row_major);
            }
    } else {
        // fused split epilogue: stage each 16x16 tile in smem, emit fp32 + bf16 hi/lo
        float* stg = (float*)sm + wid * 336;   // 16*21 = 336 floats per warp
#pragma unroll
        for (int i = 0; i < 4; i++)
#pragma unroll
            for (int j = 0; j < 4; j++) {
#pragma unroll
                for (int e = 0; e < 8; e++) acc[i][j].x[e] *= alpha;
                wmma::store_matrix_sync(stg, acc[i][j], 20, wmma::mem_row_major);
                __syncwarp();
#pragma unroll
                for (int k = 0; k < 8; k++) {
                    int e = k * 32 + lane;
                    int r = e >> 4, cc = e & 15;
                    float v = stg[r * 20 + cc];
                    size_t gi = (size_t)(bm + wm + i * 16 + r) * Nc + bn + wn + j * 16 + cc;
                    C[gi] = v;
                    __nv_bfloat16 h, l;
                    bf16split(v, h, l);
                    Chi[gi] = h;
                    Clo[gi] = l;
                }
                __syncwarp();
            }
    }
}

// ---------------------------------------------------------------------------
// Weight repack
// ---------------------------------------------------------------------------
__global__ void repack_weights(const float* __restrict__ W_de, const float* __restrict__ Wq_t,
                               const float* __restrict__ W_1,  const float* __restrict__ Wk_t,
                               const float* __restrict__ Wv_t, const float* __restrict__ W_c1,
                               const float* __restrict__ Wq_s, const float* __restrict__ Wk_s,
                               const float* __restrict__ Wv_s, const float* __restrict__ W_g) {
    int idx = blockIdx.x * 256 + threadIdx.x;
    if (idx < 2048) {
        int i = idx >> 6, o = idx & 63;
        g_WT[WT_DQ1 + idx * 4 + 0] = W_de[o * 32 + i];
        g_WT[WT_DQ1 + idx * 4 + 1] = Wq_t[o * 32 + i];
        g_WT[WT_DQ1 + idx * 4 + 2] = W_1[o * 32 + i];
        g_WT[WT_DQ1 + idx * 4 + 3] = 0.f;
    }
    if (idx < 4096) {
        int i = idx >> 6, c = idx & 63;
        g_WT[WT_KVT + idx * 2 + 0] = Wk_t[c * 64 + i];
        g_WT[WT_KVT + idx * 2 + 1] = Wv_t[c * 64 + i];
        g_WT[WT_KVS + idx * 2 + 0] = Wk_s[c * 64 + i];
        g_WT[WT_KVS + idx * 2 + 1] = Wv_s[c * 64 + i];
        g_WT[WT_QS + idx] = Wq_s[c * 64 + i];
        g_WT[WT_C1 + idx * 4 + 0] = W_c1[(c * 64 + i) * 3 + 0];
        g_WT[WT_C1 + idx * 4 + 1] = W_c1[(c * 64 + i) * 3 + 1];
        g_WT[WT_C1 + idx * 4 + 2] = W_c1[(c * 64 + i) * 3 + 2];
        g_WT[WT_C1 + idx * 4 + 3] = 0.f;
    }
    if (idx < 12288) {
        int j = idx >> 6, o = idx & 63;
        g_WT[WT_G + idx * 2 + 0] = W_g[o * 192 + j];
        g_WT[WT_G + idx * 2 + 1] = W_g[(o + 64) * 192 + j];
    }
}

// ---------------------------------------------------------------------------
// Precompute: delay(n,t), M = CS @ W_mii^T
// ---------------------------------------------------------------------------
__global__ void precompute_kernel(const float* __restrict__ CD,
                                  const float* __restrict__ Wd,
                                  const float* __restrict__ CS,
                                  const float* __restrict__ W_mii) {
    int idx = blockIdx.x * 256 + threadIdx.x;
    if (idx < NT) {
        int n = idx / TT, t = idx - n * TT;
        float a = 0.f;
#pragma unroll
        for (int d = 0; d < 16; d++) a = fmaf(CD[n * 16 + d], Wd[d * TT + t], a);
        g_delay[idx] = sigmoidf_(tanhf(a));
    }
    if (idx < NNODE * COUT) {
        int n = idx / COUT, o = idx - n * COUT;
        float a = 0.f;
#pragma unroll
        for (int e = 0; e < 16; e++) a = fmaf(CS[n * 16 + e], W_mii[o * 16 + e], a);
        g_M[idx] = a;
    }
}

__global__ void rowsum_kernel(const float* __restrict__ adj) {
    __shared__ float red[256];
    int n = blockIdx.x;
    float s = 0.f;
    for (int m = threadIdx.x; m < NNODE; m += 256) s += adj[(size_t)n * NNODE + m];
    red[threadIdx.x] = s;
    __syncthreads();
    for (int w = 128; w > 0; w >>= 1) {
        if (threadIdx.x < w) red[threadIdx.x] += red[threadIdx.x + w];
        __syncthreads();
    }
    if (threadIdx.x == 0) g_rowsum[n] = red[0];
}

// ---------------------------------------------------------------------------
// u + Ubig: writes Ubig directly as bf16 hi/lo (GEMM B operand)
// ---------------------------------------------------------------------------
__global__ void u_kernel(const float* __restrict__ x, const float* __restrict__ W_pro,
                         const float* __restrict__ b_pro, const float* __restrict__ CS) {
    int b = blockIdx.y;
    int j = blockIdx.x * 256 + threadIdx.x;
    float u = __ldg(&b_pro[0]);
#pragma unroll 8
    for (int i = 0; i < 32; i++)
        u = fmaf(__ldg(&W_pro[i]), x[((size_t)(b * 32 + i)) * NT + j], u);
    g_u[(size_t)b * NT + j] = u;
    int n = j / TT, t = j - n * TT;
#pragma unroll
    for (int e = 0; e < 16; e++) {
        float v = __ldg(&CS[n * 16 + e]) * u;
        size_t idx = (size_t)n * EB + e * (BB * TT) + b * TT + t;
        __nv_bfloat16 h, l;
        bf16split(v, h, l);
        g_Bh[idx] = h;
        g_Bl[idx] = l;
    }
}

// ---------------------------------------------------------------------------
// MEGA kernel + bf16 split write of XS for the cheby GEMM
// ---------------------------------------------------------------------------
__global__ void __launch_bounds__(256) mega_kernel(
    const float* __restrict__ x, const float* __restrict__ W_mii,
    const float* __restrict__ b_mii,
    const float* __restrict__ b_de, const float* __restrict__ bq_t,
    const float* __restrict__ b_1,  const float* __restrict__ bk_t,
    const float* __restrict__ bv_t, const float* __restrict__ b_c1,
    const float* __restrict__ bq_s, const float* __restrict__ bk_s,
    const float* __restrict__ bv_s) {
    __shared__ float xs[32][25];
    __shared__ float sD[64][25];
    __shared__ float sQ[64][25];
    __shared__ float sK[64][25];
    __shared__ float sV[64][25];
    __shared__ float sX1[64][25];
    __shared__ float sA[24][25];
    __shared__ float sZ[16][24];
    __shared__ float su[24], sdel[24], sM[64];
    __shared__ float sWm[64][16];

    int b = blockIdx.y, n = blockIdx.x, tid = threadIdx.x;
    int o = tid >> 2, q = tid & 3;

    for (int p = tid; p < 768; p += 256) {
        int i = p / 24, t = p - i * 24;
        xs[i][t] = x[((size_t)(b * 32 + i) * NNODE + n) * TT + t];
    }
    for (int p = tid; p < 384; p += 256) {
        int e = p / 24, t = p - e * 24;
        sZ[e][t] = g_Z[(size_t)n * EB + e * (BB * TT) + b * TT + t];
    }
    for (int p = tid; p < 1024; p += 256) sWm[p >> 4][p & 15] = W_mii[p];
    if (tid < 24) {
        su[tid] = g_u[(size_t)b * NT + n * TT + tid];
        sdel[tid] = g_delay[n * TT + tid];
    }
    if (tid < 64) sM[tid] = g_M[n * 64 + tid];
    __syncthreads();

    {
        float aD[6], aQ[6], aX[6];
        float bd = __ldg(&b_de[o]), bq = __ldg(&bq_t[o]), bx = __ldg(&b_1[o]);
#pragma unroll
        for (int m = 0; m < 6; m++) { aD[m] = bd; aQ[m] = bq; aX[m] = bx; }
#pragma unroll 4
        for (int i = 0; i < 32; i++) {
            float4 w = *(const float4*)&g_WT[WT_DQ1 + (i * 64 + o) * 4];
#pragma unroll
            for (int m = 0; m < 6; m++) {
                float xv = xs[i][q + 4 * m];
                aD[m] = fmaf(w.x, xv, aD[m]);
                aQ[m] = fmaf(w.y, xv, aQ[m]);
                aX[m] = fmaf(w.z, xv, aX[m]);
            }
        }
        size_t gb = (((size_t)b * 64 + o) * NNODE + n) * TT;
#pragma unroll
        for (int m = 0; m < 6; m++) {
            int t = q + 4 * m;
            sD[o][t] = aD[m] * sdel[t];
            sQ[o][t] = aQ[m];
            sX1[o][t] = aX[m];
            g_xin1[gb + t] = aX[m];
        }
    }
    __syncthreads();

    {
        float ak[6], av[6];
        float bkc = __ldg(&bk_t[o]), bvc = __ldg(&bv_t[o]);
#pragma unroll
        for (int m = 0; m < 6; m++) { ak[m] = bkc; av[m] = bvc; }
#pragma unroll 4
        for (int i = 0; i < 64; i++) {
            float2 w = *(const float2*)&g_WT[WT_KVT + (i * 64 + o) * 2];
#pragma unroll
            for (int m = 0; m < 6; m++) {
                float d = sD[i][q + 4 * m];
                ak[m] = fmaf(w.x, d, ak[m]);
                av[m] = fmaf(w.y, d, av[m]);
            }
        }
#pragma unroll
        for (int m = 0; m < 6; m++) { sK[o][q + 4 * m] = ak[m]; sV[o][q + 4 * m] = av[m]; }
    }
    __syncthreads();

    for (int p = tid; p < 576; p += 256) {
        int t = p / 24, s = p - t * 24;
        float acc = 0.f;
#pragma unroll
        for (int c = 0; c < 64; c++) acc = fmaf(sQ[c][t], sK[c][s], acc);
        sA[t][s] = acc * 0.125f;
    }
    __syncthreads();
    if (tid < 24) {
        float mx = -1e30f;
        for (int s = 0; s < 24; s++) mx = fmaxf(mx, sA[tid][s]);
        float sum = 0.f;
        for (int s = 0; s < 24; s++) { float e = __expf(sA[tid][s] - mx); sA[tid][s] = e; sum += e; }
        float inv = 1.f / sum;
        for (int s = 0; s < 24; s++) sA[tid][s] *= inv;
    }
    __syncthreads();

    for (int p = tid; p < 1536; p += 256) {
        int c = p / 24, t = p - c * 24;
        float acc = 0.f;
#pragma unroll
        for (int s = 0; s < 24; s++) acc = fmaf(sA[t][s], sV[c][s], acc);
        sX1[c][t] += acc;
    }
    __syncthreads();

    {
        float acc[6];
        float bo = __ldg(&b_c1[o]);
#pragma unroll
        for (int m = 0; m < 6; m++) acc[m] = bo;
#pragma unroll 4
        for (int i = 0; i < 64; i++) {
            float4 w = *(const float4*)&g_WT[WT_C1 + (i * 64 + o) * 4];
#pragma unroll
            for (int m = 0; m < 6; m++) {
                int t = q + 4 * m;
                float xm = (t > 0) ? sX1[i][t - 1] : 0.f;
                float x0 = sX1[i][t];
                float xp = (t < 23) ? sX1[i][t + 1] : 0.f;
                acc[m] = fmaf(w.x, xm, fmaf(w.y, x0, fmaf(w.z, xp, acc[m])));
            }
        }
#pragma unroll
        for (int m = 0; m < 6; m++) sD[o][q + 4 * m] = acc[m];
    }
    __syncthreads();

    {
        float a[6];
        float bqc = __ldg(&bq_s[o]);
#pragma unroll
        for (int m = 0; m < 6; m++) a[m] = bqc;
#pragma unroll 4
        for (int i = 0; i < 64; i++) {
            float w = __ldg(&g_WT[WT_QS + i * 64 + o]);
#pragma unroll
            for (int m = 0; m < 6; m++) a[m] = fmaf(w, sD[i][q + 4 * m], a[m]);
        }
#pragma unroll
        for (int m = 0; m < 6; m++) sQ[o][q + 4 * m] = a[m];
    }
    {
        float rs1 = 1.f + g_rowsum[n];
        for (int p = tid; p < 1536; p += 256) {
            int c = p / 24, t = p - c * 24;
            float a = __ldg(&b_mii[c]) * rs1 + su[t] * sM[c];
#pragma unroll
            for (int e = 0; e < 16; e++) a = fmaf(sWm[c][e], sZ[e][t], a);
            sV[c][t] = a;
        }
    }
    __syncthreads();

    {
        float ak[6], av[6];
        float bkc = __ldg(&bk_s[o]), bvc = __ldg(&bv_s[o]);
#pragma unroll
        for (int m = 0; m < 6; m++) { ak[m] = bkc; av[m] = bvc; }
#pragma unroll 4
        for (int i = 0; i < 64; i++) {
            float2 w = *(const float2*)&g_WT[WT_KVS + (i * 64 + o) * 2];
#pragma unroll
            for (int m = 0; m < 6; m++) {
                float d = sV[i][q + 4 * m];
                ak[m] = fmaf(w.x, d, ak[m]);
                av[m] = fmaf(w.y, d, av[m]);
            }
        }
#pragma unroll
        for (int m = 0; m < 6; m++) { sK[o][q + 4 * m] = ak[m]; sX1[o][q + 4 * m] = av[m]; }
    }
    __syncthreads();

    for (int p = tid; p < 576; p += 256) {
        int t = p / 24, s = p - t * 24;
        float acc = 0.f;
#pragma unroll
        for (int c = 0; c < 64; c++) acc = fmaf(sQ[c][t], sK[c][s], acc);
        sA[t][s] = acc * 0.125f;
    }
    __syncthreads();
    if (tid < 24) {
        float mx = -1e30f;
        for (int s = 0; s < 24; s++) mx = fmaxf(mx, sA[tid][s]);
        float sum = 0.f;
        for (int s = 0; s < 24; s++) { float e = __expf(sA[tid][s] - mx); sA[tid][s] = e; sum += e; }
        float inv = 1.f / sum;
        for (int s = 0; s < 24; s++) sA[tid][s] *= inv;
    }
    __syncthreads();

    for (int p = tid; p < 1536; p += 256) {
        int c = p / 24, t = p - c * 24;
        float acc = 0.f;
#pragma unroll
        for (int s = 0; s < 24; s++) acc = fmaf(sA[t][s], sX1[c][s], acc);
        size_t gi = (size_t)n * JCOLS + (b * 64 + c) * 24 + t;
        g_XSp[gi] = acc;
        __nv_bfloat16 h, l;
        bf16split(acc, h, l);
        g_Bh[gi] = h;
        g_Bl[gi] = l;
    }
}

// ---------------------------------------------------------------------------
// Combine
// ---------------------------------------------------------------------------
__global__ void __launch_bounds__(256) combine_kernel(const float* __restrict__ bg,
                                                      float* __restrict__ out) {
    __shared__ float xs[64][25];
    __shared__ float y1[64][25];
    __shared__ float y2[64][25];
    int b = blockIdx.y, n = blockIdx.x, tid = threadIdx.x;
    size_t row = (size_t)n * JCOLS;
    int cb = b * 64 * 24;

    for (int p = tid; p < 1536; p += 256) {
        int c = p / 24, t = p - c * 24;
        size_t g = row + cb + c * 24 + t;
        float a = g_XSp[g];
        xs[c][t] = a;
        y1[c][t] = g_Y1p[g];
        y2[c][t] = g_Y2r[g] - a;
    }
    __syncthreads();

    int o = tid & 63, q = tid >> 6;
    float f[6], gg[6];
    float bf = __ldg(&bg[o]), bgt = __ldg(&bg[o + 64]);
#pragma unroll
    for (int m = 0; m < 6; m++) { f[m] = bf; gg[m] = bgt; }
#pragma unroll 2
    for (int c = 0; c < 64; c++) {
        float2 w0 = *(const float2*)&g_WT[WT_G + ((3 * c + 0) * 64 + o) * 2];
        float2 w1 = *(const float2*)&g_WT[WT_G + ((3 * c + 1) * 64 + o) * 2];
        float2 w2 = *(const float2*)&g_WT[WT_G + ((3 * c + 2) * 64 + o) * 2];
#pragma unroll
        for (int m = 0; m < 6; m++) {
            int t = q + 4 * m;
            float a = xs[c][t], b1 = y1[c][t], b2 = y2[c][t];
            f[m]  = fmaf(w0.x, a, fmaf(w1.x, b1, fmaf(w2.x, b2, f[m])));
            gg[m] = fmaf(w0.y, a, fmaf(w1.y, b1, fmaf(w2.y, b2, gg[m])));
        }
    }
    size_t obase = (((size_t)b * 64 + o) * NNODE + n) * TT;
#pragma unroll
    for (int m = 0; m < 6; m++) {
        int t = q + 4 * m;
        out[obase + t] = (f[m] + g_xin1[obase + t]) * sigmoidf_(gg[m]);
    }
}

// ---------------------------------------------------------------------------
// Host launcher
// ---------------------------------------------------------------------------
extern "C" void kernel_launch(void* const* d_in, const int* in_sizes, int n_in,
                              void* d_out, int out_size) {
    const float* x        = (const float*)d_in[0];
    const float* supports = (const float*)d_in[1];
    const float* CD       = (const float*)d_in[2];
    const float* CS       = (const float*)d_in[3];
    const float* adj      = (const float*)d_in[4];
    const float* W_de     = (const float*)d_in[5];
    const float* b_de     = (const float*)d_in[6];
    const float* Wd       = (const float*)d_in[7];
    const float* W_pro    = (const float*)d_in[8];
    const float* b_pro    = (const float*)d_in[9];
    const float* W_mii    = (const float*)d_in[10];
    const float* b_mii    = (const float*)d_in[11];
    const float* W_1      = (const float*)d_in[12];
    const float* b_1      = (const float*)d_in[13];
    const float* Wq_t     = (const float*)d_in[14];
    const float* bq_t     = (const float*)d_in[15];
    const float* Wk_t     = (const float*)d_in[16];
    const float* bk_t     = (const float*)d_in[17];
    const float* Wv_t     = (const float*)d_in[18];
    const float* bv_t     = (const float*)d_in[19];
    const float* W_c1     = (const float*)d_in[20];
    const float* b_c1     = (const float*)d_in[21];
    const float* Wq_s     = (const float*)d_in[22];
    const float* bq_s     = (const float*)d_in[23];
    const float* Wk_s     = (const float*)d_in[24];
    const float* bk_s     = (const float*)d_in[25];
    const float* Wv_s     = (const float*)d_in[26];
    const float* bv_s     = (const float*)d_in[27];
    const float* W_g      = (const float*)d_in[28];
    const float* b_g      = (const float*)d_in[29];
    float* out = (float*)d_out;

    float *p_Z, *p_XSp, *p_Y1p, *p_Y2r;
    __nv_bfloat16 *p_Ah, *p_Al, *p_Bh, *p_Bl, *p_Ch, *p_Cl;
    cudaGetSymbolAddress((void**)&p_Z,   g_Z);
    cudaGetSymbolAddress((void**)&p_XSp, g_XSp);
    cudaGetSymbolAddress((void**)&p_Y1p, g_Y1p);
    cudaGetSymbolAddress((void**)&p_Y2r, g_Y2r);
    cudaGetSymbolAddress((void**)&p_Ah,  g_Ah);
    cudaGetSymbolAddress((void**)&p_Al,  g_Al);
    cudaGetSymbolAddress((void**)&p_Bh,  g_Bh);
    cudaGetSymbolAddress((void**)&p_Bl,  g_Bl);
    cudaGetSymbolAddress((void**)&p_Ch,  g_Ch);
    cudaGetSymbolAddress((void**)&p_Cl,  g_Cl);

    cudaFuncSetAttribute(gemm_wmma, cudaFuncAttributeMaxDynamicSharedMemorySize, GW_SMEM);

    // weight repack + small precompute
    repack_weights<<<48, 256>>>(W_de, Wq_t, W_1, Wk_t, Wv_t, W_c1,
                                Wq_s, Wk_s, Wv_s, W_g);
    precompute_kernel<<<256, 256>>>(CD, Wd, CS, W_mii);
    rowsum_kernel<<<NNODE, 256>>>(adj);

    // Z = adj @ Ubig  (u_kernel writes Ubig split directly)
    split_mat<<<(NNODE * NNODE / 4 + 255) / 256, 256>>>(adj, p_Ah, p_Al, NNODE * NNODE / 4);
    u_kernel<<<dim3(NT / 256, BB), 256>>>(x, W_pro, b_pro, CS);
    gemm_wmma<<<dim3(EB / 128, 4), 256, GW_SMEM>>>(p_Ah, p_Al, p_Bh, p_Bl, p_Z,
                                                   nullptr, nullptr, EB, 1.f);

    // fused block -> XS packed (fp32 + bf16 split)
    split_mat<<<(NNODE * NNODE / 4 + 255) / 256, 256>>>(supports, p_Ah, p_Al, NNODE * NNODE / 4);
    mega_kernel<<<dim3(NNODE, BB), 256>>>(x, W_mii, b_mii, b_de, bq_t, b_1,
                                          bk_t, bv_t, b_c1, bq_s, bk_s, bv_s);

    // cheby: Y1 = S@XS (fused split epilogue) ; Y2r = 2*S@Y1
    gemm_wmma<<<dim3(JCOLS / 128, 4), 256, GW_SMEM>>>(p_Ah, p_Al, p_Bh, p_Bl, p_Y1p,
                                                      p_Ch, p_Cl, JCOLS, 1.f);
    gemm_wmma<<<dim3(JCOLS / 128, 4), 256, GW_SMEM>>>(p_Ah, p_Al, p_Ch, p_Cl, p_Y2r,
                                                      nullptr, nullptr, JCOLS, 2.f);

    // W_g epilogue + residual + gate
    combine_kernel<<<dim3(NNODE, BB), 256>>>(b_g, out);

    (void)in_sizes; (void)n_in; (void)out_size;
}

// round 16
// speedup vs baseline: 1.1852x; 1.1852x over previous
#include <cuda_runtime.h>
#include <cuda_bf16.h>
#include <mma.h>
#include <math.h>
#include <stdint.h>

using namespace nvcuda;

// ---------------------------------------------------------------------------
// Problem constants
// ---------------------------------------------------------------------------
#define BB   16
#define CIN  32
#define COUT 64
#define NNODE 1024
#define TT   24
#define NT   (NNODE*TT)        // 24576
#define SDIM 16
#define EB   (SDIM*BB*TT)      // 6144  cols of Ubig / Z
#define JCOLS (BB*COUT*TT)     // 24576 cols of XSp / Y1p / Y2r
#define BIG  (BB*COUT*NT)      // 25165824

// packed transposed-weight scratch offsets (floats)
#define WT_DQ1 0
#define WT_KVT 8192
#define WT_C1  16384
#define WT_QS  32768
#define WT_KVS 36864
#define WT_G   45056

// ---------------------------------------------------------------------------
// Scratch (static device globals -- no allocation allowed)
// ---------------------------------------------------------------------------
__device__ __align__(16) float g_delay[NT];
__device__ __align__(16) float g_M[NNODE*COUT];
__device__ __align__(16) float g_rowsum[NNODE];
__device__ __align__(16) float g_u[BB*NT];
__device__ __align__(16) float g_Z[NNODE*EB];
__device__ __align__(16) float g_xin1[BIG];
__device__ __align__(16) float g_XSp[(size_t)NNODE*JCOLS];
__device__ __align__(16) float g_Y1p[(size_t)NNODE*JCOLS];
__device__ __align__(16) float g_Y2r[(size_t)NNODE*JCOLS];
__device__ __align__(16) float g_WT[69632];
// bf16 split operands for the tensor-core GEMMs
__device__ __align__(16) __nv_bfloat16 g_Ah[NNODE*NNODE];
__device__ __align__(16) __nv_bfloat16 g_Al[NNODE*NNODE];
__device__ __align__(16) __nv_bfloat16 g_Bh[(size_t)NNODE*JCOLS];
__device__ __align__(16) __nv_bfloat16 g_Bl[(size_t)NNODE*JCOLS];
__device__ __align__(16) __nv_bfloat16 g_Ch[(size_t)NNODE*JCOLS];
__device__ __align__(16) __nv_bfloat16 g_Cl[(size_t)NNODE*JCOLS];

__device__ __forceinline__ float sigmoidf_(float z) {
    return 1.f / (1.f + __expf(-z));
}
__device__ __forceinline__ void bf16split(float v, __nv_bfloat16& h, __nv_bfloat16& l) {
    h = __float2bfloat16(v);
    l = __float2bfloat16(v - __bfloat162float(h));
}

// ---- packed f32x2 helpers (B300 FFMA2 pipe; PTX-only, ptxas won't auto-fuse)
typedef unsigned long long u64t;
__device__ __forceinline__ u64t pk2(float a, float b) {
    u64t r; asm("mov.b64 %0, {%1, %2};" : "=l"(r) : "f"(a), "f"(b)); return r;
}
__device__ __forceinline__ u64t pk2v(float2 v) { return pk2(v.x, v.y); }
__device__ __forceinline__ void upk2(u64t v, float& a, float& b) {
    asm("mov.b64 {%0, %1}, %2;" : "=f"(a), "=f"(b) : "l"(v));
}
__device__ __forceinline__ u64t fma2_(u64t a, u64t b, u64t c) {
    u64t d; asm("fma.rn.f32x2 %0, %1, %2, %3;" : "=l"(d) : "l"(a), "l"(b), "l"(c)); return d;
}

__device__ __forceinline__ uint32_t smem_u32(const void* p) {
    uint32_t a;
    asm("{ .reg .u64 t; cvta.to.shared.u64 t, %1; cvt.u32.u64 %0, t; }" : "=r"(a) : "l"(p));
    return a;
}
#define CP_ASYNC16(dst, src) \
    asm volatile("cp.async.ca.shared.global [%0], [%1], 16;" :: "r"(dst), "l"(src))
#define CP_COMMIT() asm volatile("cp.async.commit_group;" ::: "memory")
#define CP_WAIT1()  asm volatile("cp.async.wait_group 1;" ::: "memory")
#define CP_WAIT0()  asm volatile("cp.async.wait_group 0;" ::: "memory")

// ---------------------------------------------------------------------------
// split fp32 matrix -> bf16 hi/lo (vectorized by 4) -- used for adj/supports
// ---------------------------------------------------------------------------
__global__ void split_mat(const float* __restrict__ src, __nv_bfloat16* __restrict__ hi,
                          __nv_bfloat16* __restrict__ lo, int n4) {
    int i = blockIdx.x * 256 + threadIdx.x;
    if (i >= n4) return;
    float4 v = ((const float4*)src)[i];
    __nv_bfloat16 h0, h1, h2, h3, l0, l1, l2, l3;
    bf16split(v.x, h0, l0); bf16split(v.y, h1, l1);
    bf16split(v.z, h2, l2); bf16split(v.w, h3, l3);
    uint2 ph, pl;
    ph.x = (uint32_t)__bfloat16_as_ushort(h0) | ((uint32_t)__bfloat16_as_ushort(h1) << 16);
    ph.y = (uint32_t)__bfloat16_as_ushort(h2) | ((uint32_t)__bfloat16_as_ushort(h3) << 16);
    pl.x = (uint32_t)__bfloat16_as_ushort(l0) | ((uint32_t)__bfloat16_as_ushort(l1) << 16);
    pl.y = (uint32_t)__bfloat16_as_ushort(l2) | ((uint32_t)__bfloat16_as_ushort(l3) << 16);
    *(uint2*)&hi[(size_t)i * 4] = ph;
    *(uint2*)&lo[(size_t)i * 4] = pl;
}

// ---------------------------------------------------------------------------
// wmma bf16 split-precision GEMM (R14 config: 128x128 CTA, 64x32 warp tiles,
// cp.async double-buffered). C = Ah*Bh + Ah*Bl + Al*Bh in fp32.
// ---------------------------------------------------------------------------
#define GW_SMEM 75776

__global__ void __launch_bounds__(256)
gemm_wmma(const __nv_bfloat16* __restrict__ Ah, const __nv_bfloat16* __restrict__ Al,
          const __nv_bfloat16* __restrict__ Bh, const __nv_bfloat16* __restrict__ Bl,
          float* __restrict__ C, __nv_bfloat16* __restrict__ Chi,
          __nv_bfloat16* __restrict__ Clo, int Nc, float alpha) {
    extern __shared__ __align__(16) __nv_bfloat16 sm[];
    __nv_bfloat16* sAh = sm;
    __nv_bfloat16* sAl = sm + 10240;
    __nv_bfloat16* sBh = sm + 20480;
    __nv_bfloat16* sBl = sm + 29184;
    uint32_t uAh = smem_u32(sAh), uAl = smem_u32(sAl);
    uint32_t uBh = smem_u32(sBh), uBl = smem_u32(sBl);

    int tid = threadIdx.x;
    int wid = tid >> 5, lane = tid & 31;
    int bm = blockIdx.y * 128, bn = blockIdx.x * 128;
    int wm = (wid >> 2) * 64;
    int wn = (wid & 3) * 32;

    wmma::fragment<wmma::accumulator, 16, 16, 16, float> acc[4][2];
#pragma unroll
    for (int i = 0; i < 4; i++)
#pragma unroll
        for (int j = 0; j < 2; j++) wmma::fill_fragment(acc[i][j], 0.f);

    int ar = tid >> 1;
    int ac = (tid & 1) << 4;
    int br = tid >> 3;
    int bc = (tid & 7) << 4;

#define ISSUE(ch, s) do {                                                            \
    int _k0 = (ch) * 32;                                                             \
    const __nv_bfloat16* gA = Ah + (size_t)(bm + ar) * 1024 + _k0 + ac;              \
    const __nv_bfloat16* gAl2 = Al + (size_t)(bm + ar) * 1024 + _k0 + ac;            \
    uint32_t dA = uAh + (((s) * 128 + ar) * 40 + ac) * 2;                            \
    uint32_t dAl2 = uAl + (((s) * 128 + ar) * 40 + ac) * 2;                          \
    CP_ASYNC16(dA, gA); CP_ASYNC16(dA + 16, gA + 8);                                 \
    CP_ASYNC16(dAl2, gAl2); CP_ASYNC16(dAl2 + 16, gAl2 + 8);                         \
    const __nv_bfloat16* gB = Bh + (size_t)(_k0 + br) * Nc + bn + bc;                \
    const __nv_bfloat16* gBl2 = Bl + (size_t)(_k0 + br) * Nc + bn + bc;              \
    uint32_t dB = uBh + (((s) * 32 + br) * 136 + bc) * 2;                            \
    uint32_t dBl2 = uBl + (((s) * 32 + br) * 136 + bc) * 2;                          \
    CP_ASYNC16(dB, gB); CP_ASYNC16(dB + 16, gB + 8);                                 \
    CP_ASYNC16(dBl2, gBl2); CP_ASYNC16(dBl2 + 16, gBl2 + 8);                         \
} while (0)

    ISSUE(0, 0);
    CP_COMMIT();

    for (int ch = 0; ch < 32; ch++) {
        int s = ch & 1;
        if (ch + 1 < 32) {
            ISSUE(ch + 1, (ch + 1) & 1);
            CP_COMMIT();
            CP_WAIT1();
        } else {
            CP_WAIT0();
        }
        __syncthreads();

#pragma unroll
        for (int kk = 0; kk < 32; kk += 16) {
            wmma::fragment<wmma::matrix_a, 16, 16, 16, __nv_bfloat16, wmma::row_major> fah[4], fal[4];
            wmma::fragment<wmma::matrix_b, 16, 16, 16, __nv_bfloat16, wmma::row_major> fbh[2], fbl[2];
#pragma unroll
            for (int i = 0; i < 4; i++) {
                wmma::load_matrix_sync(fah[i], &sAh[(s * 128 + wm + i * 16) * 40 + kk], 40);
                wmma::load_matrix_sync(fal[i], &sAl[(s * 128 + wm + i * 16) * 40 + kk], 40);
            }
#pragma unroll
            for (int j = 0; j < 2; j++) {
                wmma::load_matrix_sync(fbh[j], &sBh[(s * 32 + kk) * 136 + wn + j * 16], 136);
                wmma::load_matrix_sync(fbl[j], &sBl[(s * 32 + kk) * 136 + wn + j * 16], 136);
            }
#pragma unroll
            for (int i = 0; i < 4; i++)
#pragma unroll
                for (int j = 0; j < 2; j++) {
                    wmma::mma_sync(acc[i][j], fah[i], fbh[j], acc[i][j]);
                    wmma::mma_sync(acc[i][j], fah[i], fbl[j], acc[i][j]);
                    wmma::mma_sync(acc[i][j], fal[i], fbh[j], acc[i][j]);
                }
        }
        __syncthreads();
    }
#undef ISSUE

    if (Chi == nullptr) {
#pragma unroll
        for (int i = 0; i < 4; i++)
#pragma unroll
            for (int j = 0; j < 2; j++) {
#pragma unroll
                for (int e = 0; e < 8; e++) acc[i][j].x[e] *= alpha;
                wmma::store_matrix_sync(&C[(size_t)(bm + wm + i * 16) * Nc + bn + wn + j * 16],
                                        acc[i][j], Nc, wmma::mem_row_major);
            }
    } else {
        float* stg = (float*)sm + wid * 336;
#pragma unroll
        for (int i = 0; i < 4; i++)
#pragma unroll
            for (int j = 0; j < 2; j++) {
#pragma unroll
                for (int e = 0; e < 8; e++) acc[i][j].x[e] *= alpha;
                wmma::store_matrix_sync(stg, acc[i][j], 20, wmma::mem_row_major);
                __syncwarp();
#pragma unroll
                for (int k = 0; k < 8; k++) {
                    int e = k * 32 + lane;
                    int r = e >> 4, cc = e & 15;
                    float v = stg[r * 20 + cc];
                    size_t gi = (size_t)(bm + wm + i * 16 + r) * Nc + bn + wn + j * 16 + cc;
                    C[gi] = v;
                    __nv_bfloat16 h, l;
                    bf16split(v, h, l);
                    Chi[gi] = h;
                    Clo[gi] = l;
                }
                __syncwarp();
            }
    }
}

// ---------------------------------------------------------------------------
// Weight repack
// ---------------------------------------------------------------------------
__global__ void repack_weights(const float* __restrict__ W_de, const float* __restrict__ Wq_t,
                               const float* __restrict__ W_1,  const float* __restrict__ Wk_t,
                               const float* __restrict__ Wv_t, const float* __restrict__ W_c1,
                               const float* __restrict__ Wq_s, const float* __restrict__ Wk_s,
                               const float* __restrict__ Wv_s, const float* __restrict__ W_g) {
    int idx = blockIdx.x * 256 + threadIdx.x;
    if (idx < 2048) {
        int i = idx >> 6, o = idx & 63;
        g_WT[WT_DQ1 + idx * 4 + 0] = W_de[o * 32 + i];
        g_WT[WT_DQ1 + idx * 4 + 1] = Wq_t[o * 32 + i];
        g_WT[WT_DQ1 + idx * 4 + 2] = W_1[o * 32 + i];
        g_WT[WT_DQ1 + idx * 4 + 3] = 0.f;
    }
    if (idx < 4096) {
        int i = idx >> 6, c = idx & 63;
        g_WT[WT_KVT + idx * 2 + 0] = Wk_t[c * 64 + i];
        g_WT[WT_KVT + idx * 2 + 1] = Wv_t[c * 64 + i];
        g_WT[WT_KVS + idx * 2 + 0] = Wk_s[c * 64 + i];
        g_WT[WT_KVS + idx * 2 + 1] = Wv_s[c * 64 + i];
        g_WT[WT_QS + idx] = Wq_s[c * 64 + i];
        g_WT[WT_C1 + idx * 4 + 0] = W_c1[(c * 64 + i) * 3 + 0];
        g_WT[WT_C1 + idx * 4 + 1] = W_c1[(c * 64 + i) * 3 + 1];
        g_WT[WT_C1 + idx * 4 + 2] = W_c1[(c * 64 + i) * 3 + 2];
        g_WT[WT_C1 + idx * 4 + 3] = 0.f;
    }
    if (idx < 12288) {
        int j = idx >> 6, o = idx & 63;
        g_WT[WT_G + idx * 2 + 0] = W_g[o * 192 + j];
        g_WT[WT_G + idx * 2 + 1] = W_g[(o + 64) * 192 + j];
    }
}

// ---------------------------------------------------------------------------
// Precompute: delay(n,t), M = CS @ W_mii^T
// ---------------------------------------------------------------------------
__global__ void precompute_kernel(const float* __restrict__ CD,
                                  const float* __restrict__ Wd,
                                  const float* __restrict__ CS,
                                  const float* __restrict__ W_mii) {
    int idx = blockIdx.x * 256 + threadIdx.x;
    if (idx < NT) {
        int n = idx / TT, t = idx - n * TT;
        float a = 0.f;
#pragma unroll
        for (int d = 0; d < 16; d++) a = fmaf(CD[n * 16 + d], Wd[d * TT + t], a);
        g_delay[idx] = sigmoidf_(tanhf(a));
    }
    if (idx < NNODE * COUT) {
        int n = idx / COUT, o = idx - n * COUT;
        float a = 0.f;
#pragma unroll
        for (int e = 0; e < 16; e++) a = fmaf(CS[n * 16 + e], W_mii[o * 16 + e], a);
        g_M[idx] = a;
    }
}

__global__ void rowsum_kernel(const float* __restrict__ adj) {
    __shared__ float red[256];
    int n = blockIdx.x;
    float s = 0.f;
    for (int m = threadIdx.x; m < NNODE; m += 256) s += adj[(size_t)n * NNODE + m];
    red[threadIdx.x] = s;
    __syncthreads();
    for (int w = 128; w > 0; w >>= 1) {
        if (threadIdx.x < w) red[threadIdx.x] += red[threadIdx.x + w];
        __syncthreads();
    }
    if (threadIdx.x == 0) g_rowsum[n] = red[0];
}

// ---------------------------------------------------------------------------
// u + Ubig: writes Ubig directly as bf16 hi/lo (GEMM B operand)
// ---------------------------------------------------------------------------
__global__ void u_kernel(const float* __restrict__ x, const float* __restrict__ W_pro,
                         const float* __restrict__ b_pro, const float* __restrict__ CS) {
    int b = blockIdx.y;
    int j = blockIdx.x * 256 + threadIdx.x;
    float u = __ldg(&b_pro[0]);
#pragma unroll 8
    for (int i = 0; i < 32; i++)
        u = fmaf(__ldg(&W_pro[i]), x[((size_t)(b * 32 + i)) * NT + j], u);
    g_u[(size_t)b * NT + j] = u;
    int n = j / TT, t = j - n * TT;
#pragma unroll
    for (int e = 0; e < 16; e++) {
        float v = __ldg(&CS[n * 16 + e]) * u;
        size_t idx = (size_t)n * EB + e * (BB * TT) + b * TT + t;
        __nv_bfloat16 h, l;
        bf16split(v, h, l);
        g_Bh[idx] = h;
        g_Bl[idx] = l;
    }
}

// ---------------------------------------------------------------------------
// MEGA kernel: f32x2 (FFMA2) inner loops, per-thread t = 6q..6q+5.
// ---------------------------------------------------------------------------
__global__ void __launch_bounds__(256) mega_kernel(
    const float* __restrict__ x, const float* __restrict__ W_mii,
    const float* __restrict__ b_mii,
    const float* __restrict__ b_de, const float* __restrict__ bq_t,
    const float* __restrict__ b_1,  const float* __restrict__ bk_t,
    const float* __restrict__ bv_t, const float* __restrict__ b_c1,
    const float* __restrict__ bq_s, const float* __restrict__ bk_s,
    const float* __restrict__ bv_s) {
    __shared__ float xs[32][26];
    __shared__ float sD[64][26];
    __shared__ float sQ[64][26];
    __shared__ float sK[64][26];
    __shared__ float sV[64][26];
    __shared__ float sX1[64][26];
    __shared__ float sA[24][25];
    __shared__ float sZ[16][24];
    __shared__ float su[24], sdel[24], sM[64];
    __shared__ float sWm[64][16];

    int b = blockIdx.y, n = blockIdx.x, tid = threadIdx.x;
    int o = tid >> 2, q = tid & 3;
    int tb = q * 6;

    for (int p = tid; p < 768; p += 256) {
        int i = p / 24, t = p - i * 24;
        xs[i][t] = x[((size_t)(b * 32 + i) * NNODE + n) * TT + t];
    }
    for (int p = tid; p < 384; p += 256) {
        int e = p / 24, t = p - e * 24;
        sZ[e][t] = g_Z[(size_t)n * EB + e * (BB * TT) + b * TT + t];
    }
    for (int p = tid; p < 1024; p += 256) sWm[p >> 4][p & 15] = W_mii[p];
    if (tid < 24) {
        su[tid] = g_u[(size_t)b * NT + n * TT + tid];
        sdel[tid] = g_delay[n * TT + tid];
    }
    if (tid < 64) sM[tid] = g_M[n * 64 + tid];
    __syncthreads();

    // ---- D(*delay), Qt, xin1 ----
    {
        u64t aD[3], aQ[3], aX[3];
        float bd = __ldg(&b_de[o]), bq = __ldg(&bq_t[o]), bx = __ldg(&b_1[o]);
#pragma unroll
        for (int j = 0; j < 3; j++) { aD[j] = pk2(bd, bd); aQ[j] = pk2(bq, bq); aX[j] = pk2(bx, bx); }
#pragma unroll 4
        for (int i = 0; i < 32; i++) {
            float4 w = *(const float4*)&g_WT[WT_DQ1 + (i * 64 + o) * 4];
            u64t wx = pk2(w.x, w.x), wy = pk2(w.y, w.y), wz = pk2(w.z, w.z);
#pragma unroll
            for (int j = 0; j < 3; j++) {
                u64t X = pk2v(*(const float2*)&xs[i][tb + 2 * j]);
                aD[j] = fma2_(wx, X, aD[j]);
                aQ[j] = fma2_(wy, X, aQ[j]);
                aX[j] = fma2_(wz, X, aX[j]);
            }
        }
        size_t gb = (((size_t)b * 64 + o) * NNODE + n) * TT;
#pragma unroll
        for (int j = 0; j < 3; j++) {
            int t0 = tb + 2 * j;
            float d0, d1, q0, q1, x0, x1;
            upk2(aD[j], d0, d1); upk2(aQ[j], q0, q1); upk2(aX[j], x0, x1);
            sD[o][t0] = d0 * sdel[t0]; sD[o][t0 + 1] = d1 * sdel[t0 + 1];
            sQ[o][t0] = q0; sQ[o][t0 + 1] = q1;
            sX1[o][t0] = x0; sX1[o][t0 + 1] = x1;
            *(float2*)&g_xin1[gb + t0] = make_float2(x0, x1);
        }
    }
    __syncthreads();

    // ---- Kt,Vt = conv1x1(D) ----
    {
        u64t ak[3], av[3];
        float bk0 = __ldg(&bk_t[o]), bv0 = __ldg(&bv_t[o]);
#pragma unroll
        for (int j = 0; j < 3; j++) { ak[j] = pk2(bk0, bk0); av[j] = pk2(bv0, bv0); }
#pragma unroll 4
        for (int i = 0; i < 64; i++) {
            float2 w = *(const float2*)&g_WT[WT_KVT + (i * 64 + o) * 2];
            u64t wk = pk2(w.x, w.x), wv = pk2(w.y, w.y);
#pragma unroll
            for (int j = 0; j < 3; j++) {
                u64t D = pk2v(*(const float2*)&sD[i][tb + 2 * j]);
                ak[j] = fma2_(wk, D, ak[j]);
                av[j] = fma2_(wv, D, av[j]);
            }
        }
#pragma unroll
        for (int j = 0; j < 3; j++) {
            int t0 = tb + 2 * j;
            float k0, k1, v0, v1;
            upk2(ak[j], k0, k1); upk2(av[j], v0, v1);
            sK[o][t0] = k0; sK[o][t0 + 1] = k1;
            sV[o][t0] = v0; sV[o][t0 + 1] = v1;
        }
    }
    __syncthreads();

    for (int p = tid; p < 576; p += 256) {
        int t = p / 24, s = p - t * 24;
        float acc = 0.f;
#pragma unroll
        for (int c = 0; c < 64; c++) acc = fmaf(sQ[c][t], sK[c][s], acc);
        sA[t][s] = acc * 0.125f;
    }
    __syncthreads();
    if (tid < 24) {
        float mx = -1e30f;
        for (int s = 0; s < 24; s++) mx = fmaxf(mx, sA[tid][s]);
        float sum = 0.f;
        for (int s = 0; s < 24; s++) { float e = __expf(sA[tid][s] - mx); sA[tid][s] = e; sum += e; }
        float inv = 1.f / sum;
        for (int s = 0; s < 24; s++) sA[tid][s] *= inv;
    }
    __syncthreads();

    for (int p = tid; p < 1536; p += 256) {
        int c = p / 24, t = p - c * 24;
        float acc = 0.f;
#pragma unroll
        for (int s = 0; s < 24; s++) acc = fmaf(sA[t][s], sV[c][s], acc);
        sX1[c][t] += acc;
    }
    __syncthreads();

    // ---- temporal conv (k=3, pad 1): sX1 -> sD ----
    {
        u64t A[3];
        float bo = __ldg(&b_c1[o]);
#pragma unroll
        for (int j = 0; j < 3; j++) A[j] = pk2(bo, bo);
#pragma unroll 4
        for (int i = 0; i < 64; i++) {
            float4 w = *(const float4*)&g_WT[WT_C1 + (i * 64 + o) * 4];
            u64t w0 = pk2(w.x, w.x), w1 = pk2(w.y, w.y), w2 = pk2(w.z, w.z);
#pragma unroll
            for (int j = 0; j < 3; j++) {
                int t0 = tb + 2 * j;
                float2 v0 = *(const float2*)&sX1[i][t0];
                float xm = (t0 > 0) ? sX1[i][t0 - 1] : 0.f;
                float xp = (t0 < 22) ? sX1[i][t0 + 2] : 0.f;
                A[j] = fma2_(w0, pk2(xm, v0.x), A[j]);
                A[j] = fma2_(w1, pk2(v0.x, v0.y), A[j]);
                A[j] = fma2_(w2, pk2(v0.y, xp), A[j]);
            }
        }
#pragma unroll
        for (int j = 0; j < 3; j++) {
            int t0 = tb + 2 * j;
            float a0, a1;
            upk2(A[j], a0, a1);
            sD[o][t0] = a0; sD[o][t0 + 1] = a1;
        }
    }
    __syncthreads();

    // ---- Qs = conv1x1(x1) -> sQ ----
    {
        u64t A[3];
        float bqc = __ldg(&bq_s[o]);
#pragma unroll
        for (int j = 0; j < 3; j++) A[j] = pk2(bqc, bqc);
#pragma unroll 4
        for (int i = 0; i < 64; i++) {
            float w = __ldg(&g_WT[WT_QS + i * 64 + o]);
            u64t ww = pk2(w, w);
#pragma unroll
            for (int j = 0; j < 3; j++)
                A[j] = fma2_(ww, pk2v(*(const float2*)&sD[i][tb + 2 * j]), A[j]);
        }
#pragma unroll
        for (int j = 0; j < 3; j++) {
            int t0 = tb + 2 * j;
            float a0, a1;
            upk2(A[j], a0, a1);
            sQ[o][t0] = a0; sQ[o][t0 + 1] = a1;
        }
    }
    // ---- S (rank-16 recon) -> sV ----
    {
        float rs1 = 1.f + g_rowsum[n];
        for (int p = tid; p < 1536; p += 256) {
            int c = p / 24, t = p - c * 24;
            float a = __ldg(&b_mii[c]) * rs1 + su[t] * sM[c];
#pragma unroll
            for (int e = 0; e < 16; e++) a = fmaf(sWm[c][e], sZ[e][t], a);
            sV[c][t] = a;
        }
    }
    __syncthreads();

    // ---- Ks,Vs = conv1x1(S): sV -> sK, sX1 ----
    {
        u64t ak[3], av[3];
        float bk0 = __ldg(&bk_s[o]), bv0 = __ldg(&bv_s[o]);
#pragma unroll
        for (int j = 0; j < 3; j++) { ak[j] = pk2(bk0, bk0); av[j] = pk2(bv0, bv0); }
#pragma unroll 4
        for (int i = 0; i < 64; i++) {
            float2 w = *(const float2*)&g_WT[WT_KVS + (i * 64 + o) * 2];
            u64t wk = pk2(w.x, w.x), wv = pk2(w.y, w.y);
#pragma unroll
            for (int j = 0; j < 3; j++) {
                u64t D = pk2v(*(const float2*)&sV[i][tb + 2 * j]);
                ak[j] = fma2_(wk, D, ak[j]);
                av[j] = fma2_(wv, D, av[j]);
            }
        }
#pragma unroll
        for (int j = 0; j < 3; j++) {
            int t0 = tb + 2 * j;
            float k0, k1, v0, v1;
            upk2(ak[j], k0, k1); upk2(av[j], v0, v1);
            sK[o][t0] = k0; sK[o][t0 + 1] = k1;
            sX1[o][t0] = v0; sX1[o][t0 + 1] = v1;
        }
    }
    __syncthreads();

    for (int p = tid; p < 576; p += 256) {
        int t = p / 24, s = p - t * 24;
        float acc = 0.f;
#pragma unroll
        for (int c = 0; c < 64; c++) acc = fmaf(sQ[c][t], sK[c][s], acc);
        sA[t][s] = acc * 0.125f;
    }
    __syncthreads();
    if (tid < 24) {
        float mx = -1e30f;
        for (int s = 0; s < 24; s++) mx = fmaxf(mx, sA[tid][s]);
        float sum = 0.f;
        for (int s = 0; s < 24; s++) { float e = __expf(sA[tid][s] - mx); sA[tid][s] = e; sum += e; }
        float inv = 1.f / sum;
        for (int s = 0; s < 24; s++) sA[tid][s] *= inv;
    }
    __syncthreads();

    for (int p = tid; p < 1536; p += 256) {
        int c = p / 24, t = p - c * 24;
        float acc = 0.f;
#pragma unroll
        for (int s = 0; s < 24; s++) acc = fmaf(sA[t][s], sX1[c][s], acc);
        size_t gi = (size_t)n * JCOLS + (b * 64 + c) * 24 + t;
        g_XSp[gi] = acc;
        __nv_bfloat16 h, l;
        bf16split(acc, h, l);
        g_Bh[gi] = h;
        g_Bl[gi] = l;
    }
}

// ---------------------------------------------------------------------------
// Combine: f32x2 inner loop, per-thread t = 6q..6q+5.
// ---------------------------------------------------------------------------
__global__ void __launch_bounds__(256) combine_kernel(const float* __restrict__ bg,
                                                      float* __restrict__ out) {
    __shared__ float xs[64][26];
    __shared__ float y1[64][26];
    __shared__ float y2[64][26];
    int b = blockIdx.y, n = blockIdx.x, tid = threadIdx.x;
    size_t row = (size_t)n * JCOLS;
    int cb = b * 64 * 24;

    for (int p = tid; p < 1536; p += 256) {
        int c = p / 24, t = p - c * 24;
        size_t g = row + cb + c * 24 + t;
        float a = g_XSp[g];
        xs[c][t] = a;
        y1[c][t] = g_Y1p[g];
        y2[c][t] = g_Y2r[g] - a;
    }
    __syncthreads();

    int o = tid & 63, q = tid >> 6;
    int tb = q * 6;
    u64t F[3], G[3];
    float bf = __ldg(&bg[o]), bgt = __ldg(&bg[o + 64]);
#pragma unroll
    for (int j = 0; j < 3; j++) { F[j] = pk2(bf, bf); G[j] = pk2(bgt, bgt); }
#pragma unroll 2
    for (int c = 0; c < 64; c++) {
        float2 w0 = *(const float2*)&g_WT[WT_G + ((3 * c + 0) * 64 + o) * 2];
        float2 w1 = *(const float2*)&g_WT[WT_G + ((3 * c + 1) * 64 + o) * 2];
        float2 w2 = *(const float2*)&g_WT[WT_G + ((3 * c + 2) * 64 + o) * 2];
        u64t w0f = pk2(w0.x, w0.x), w0g = pk2(w0.y, w0.y);
        u64t w1f = pk2(w1.x, w1.x), w1g = pk2(w1.y, w1.y);
        u64t w2f = pk2(w2.x, w2.x), w2g = pk2(w2.y, w2.y);
#pragma unroll
        for (int j = 0; j < 3; j++) {
            u64t A  = pk2v(*(const float2*)&xs[c][tb + 2 * j]);
            u64t B1 = pk2v(*(const float2*)&y1[c][tb + 2 * j]);
            u64t B2 = pk2v(*(const float2*)&y2[c][tb + 2 * j]);
            F[j] = fma2_(w0f, A, F[j]);
            F[j] = fma2_(w1f, B1, F[j]);
            F[j] = fma2_(w2f, B2, F[j]);
            G[j] = fma2_(w0g, A, G[j]);
            G[j] = fma2_(w1g, B1, G[j]);
            G[j] = fma2_(w2g, B2, G[j]);
        }
    }
    size_t obase = (((size_t)b * 64 + o) * NNODE + n) * TT;
#pragma unroll
    for (int j = 0; j < 3; j++) {
        int t0 = tb + 2 * j;
        float f0, f1, g0, g1;
        upk2(F[j], f0, f1); upk2(G[j], g0, g1);
        float2 xi = *(const float2*)&g_xin1[obase + t0];
        float2 ov;
        ov.x = (f0 + xi.x) * sigmoidf_(g0);
        ov.y = (f1 + xi.y) * sigmoidf_(g1);
        *(float2*)&out[obase + t0] = ov;
    }
}

// ---------------------------------------------------------------------------
// Host launcher
// ---------------------------------------------------------------------------
extern "C" void kernel_launch(void* const* d_in, const int* in_sizes, int n_in,
                              void* d_out, int out_size) {
    const float* x        = (const float*)d_in[0];
    const float* supports = (const float*)d_in[1];
    const float* CD       = (const float*)d_in[2];
    const float* CS       = (const float*)d_in[3];
    const float* adj      = (const float*)d_in[4];
    const float* W_de     = (const float*)d_in[5];
    const float* b_de     = (const float*)d_in[6];
    const float* Wd       = (const float*)d_in[7];
    const float* W_pro    = (const float*)d_in[8];
    const float* b_pro    = (const float*)d_in[9];
    const float* W_mii    = (const float*)d_in[10];
    const float* b_mii    = (const float*)d_in[11];
    const float* W_1      = (const float*)d_in[12];
    const float* b_1      = (const float*)d_in[13];
    const float* Wq_t     = (const float*)d_in[14];
    const float* bq_t     = (const float*)d_in[15];
    const float* Wk_t     = (const float*)d_in[16];
    const float* bk_t     = (const float*)d_in[17];
    const float* Wv_t     = (const float*)d_in[18];
    const float* bv_t     = (const float*)d_in[19];
    const float* W_c1     = (const float*)d_in[20];
    const float* b_c1     = (const float*)d_in[21];
    const float* Wq_s     = (const float*)d_in[22];
    const float* bq_s     = (const float*)d_in[23];
    const float* Wk_s     = (const float*)d_in[24];
    const float* bk_s     = (const float*)d_in[25];
    const float* Wv_s     = (const float*)d_in[26];
    const float* bv_s     = (const float*)d_in[27];
    const float* W_g      = (const float*)d_in[28];
    const float* b_g      = (const float*)d_in[29];
    float* out = (float*)d_out;

    float *p_Z, *p_XSp, *p_Y1p, *p_Y2r;
    __nv_bfloat16 *p_Ah, *p_Al, *p_Bh, *p_Bl, *p_Ch, *p_Cl;
    cudaGetSymbolAddress((void**)&p_Z,   g_Z);
    cudaGetSymbolAddress((void**)&p_XSp, g_XSp);
    cudaGetSymbolAddress((void**)&p_Y1p, g_Y1p);
    cudaGetSymbolAddress((void**)&p_Y2r, g_Y2r);
    cudaGetSymbolAddress((void**)&p_Ah,  g_Ah);
    cudaGetSymbolAddress((void**)&p_Al,  g_Al);
    cudaGetSymbolAddress((void**)&p_Bh,  g_Bh);
    cudaGetSymbolAddress((void**)&p_Bl,  g_Bl);
    cudaGetSymbolAddress((void**)&p_Ch,  g_Ch);
    cudaGetSymbolAddress((void**)&p_Cl,  g_Cl);

    cudaFuncSetAttribute(gemm_wmma, cudaFuncAttributeMaxDynamicSharedMemorySize, GW_SMEM);

    // weight repack + small precompute
    repack_weights<<<48, 256>>>(W_de, Wq_t, W_1, Wk_t, Wv_t, W_c1,
                                Wq_s, Wk_s, Wv_s, W_g);
    precompute_kernel<<<256, 256>>>(CD, Wd, CS, W_mii);
    rowsum_kernel<<<NNODE, 256>>>(adj);

    // Z = adj @ Ubig  (u_kernel writes Ubig split directly)
    split_mat<<<(NNODE * NNODE / 4 + 255) / 256, 256>>>(adj, p_Ah, p_Al, NNODE * NNODE / 4);
    u_kernel<<<dim3(NT / 256, BB), 256>>>(x, W_pro, b_pro, CS);
    gemm_wmma<<<dim3(EB / 128, 8), 256, GW_SMEM>>>(p_Ah, p_Al, p_Bh, p_Bl, p_Z,
                                                   nullptr, nullptr, EB, 1.f);

    // fused block -> XS packed (fp32 + bf16 split)
    split_mat<<<(NNODE * NNODE / 4 + 255) / 256, 256>>>(supports, p_Ah, p_Al, NNODE * NNODE / 4);
    mega_kernel<<<dim3(NNODE, BB), 256>>>(x, W_mii, b_mii, b_de, bq_t, b_1,
                                          bk_t, bv_t, b_c1, bq_s, bk_s, bv_s);

    // cheby: Y1 = S@XS (fused split epilogue) ; Y2r = 2*S@Y1
    gemm_wmma<<<dim3(JCOLS / 128, 8), 256, GW_SMEM>>>(p_Ah, p_Al, p_Bh, p_Bl, p_Y1p,
                                                      p_Ch, p_Cl, JCOLS, 1.f);
    gemm_wmma<<<dim3(JCOLS / 128, 8), 256, GW_SMEM>>>(p_Ah, p_Al, p_Ch, p_Cl, p_Y2r,
                                                      nullptr, nullptr, JCOLS, 2.f);

    // W_g epilogue + residual + gate
    combine_kernel<<<dim3(NNODE, BB), 256>>>(b_g, out);

    (void)in_sizes; (void)n_in; (void)out_size;
}

// round 17
// speedup vs baseline: 1.1974x; 1.0104x over previous
#include <cuda_runtime.h>
#include <cuda_bf16.h>
#include <mma.h>
#include <math.h>
#include <stdint.h>

using namespace nvcuda;

// ---------------------------------------------------------------------------
// Problem constants
// ---------------------------------------------------------------------------
#define BB   16
#define CIN  32
#define COUT 64
#define NNODE 1024
#define TT   24
#define NT   (NNODE*TT)        // 24576
#define SDIM 16
#define EB   (SDIM*BB*TT)      // 6144  cols of Ubig / Z
#define JCOLS (BB*COUT*TT)     // 24576 cols of XSp / Y1p / Y2r
#define BIG  (BB*COUT*NT)      // 25165824

// packed transposed-weight scratch offsets (floats)
#define WT_DQ1 0
#define WT_KVT 8192
#define WT_C1  16384
#define WT_QS  32768
#define WT_KVS 36864
#define WT_G   45056

// ---------------------------------------------------------------------------
// Scratch (static device globals -- no allocation allowed)
// ---------------------------------------------------------------------------
__device__ __align__(16) float g_delay[NT];
__device__ __align__(16) float g_M[NNODE*COUT];
__device__ __align__(16) float g_rowsum[NNODE];
__device__ __align__(16) float g_u[BB*NT];
__device__ __align__(16) float g_Z[NNODE*EB];
__device__ __align__(16) float g_xin1[BIG];
__device__ __align__(16) float g_XSp[(size_t)NNODE*JCOLS];
__device__ __align__(16) float g_Y1p[(size_t)NNODE*JCOLS];
__device__ __align__(16) float g_Y2r[(size_t)NNODE*JCOLS];
__device__ __align__(16) float g_WT[69632];
// bf16 split operands for the tensor-core GEMMs
__device__ __align__(16) __nv_bfloat16 g_Ah[NNODE*NNODE];
__device__ __align__(16) __nv_bfloat16 g_Al[NNODE*NNODE];
__device__ __align__(16) __nv_bfloat16 g_Bh[(size_t)NNODE*JCOLS];
__device__ __align__(16) __nv_bfloat16 g_Bl[(size_t)NNODE*JCOLS];
__device__ __align__(16) __nv_bfloat16 g_Ch[(size_t)NNODE*JCOLS];
__device__ __align__(16) __nv_bfloat16 g_Cl[(size_t)NNODE*JCOLS];

__device__ __forceinline__ float sigmoidf_(float z) {
    return 1.f / (1.f + __expf(-z));
}
__device__ __forceinline__ void bf16split(float v, __nv_bfloat16& h, __nv_bfloat16& l) {
    h = __float2bfloat16(v);
    l = __float2bfloat16(v - __bfloat162float(h));
}

// ---- packed f32x2 helpers (B300 FFMA2 pipe; PTX-only, ptxas won't auto-fuse)
typedef unsigned long long u64t;
__device__ __forceinline__ u64t pk2(float a, float b) {
    u64t r; asm("mov.b64 %0, {%1, %2};" : "=l"(r) : "f"(a), "f"(b)); return r;
}
__device__ __forceinline__ u64t pk2v(float2 v) { return pk2(v.x, v.y); }
__device__ __forceinline__ void upk2(u64t v, float& a, float& b) {
    asm("mov.b64 {%0, %1}, %2;" : "=f"(a), "=f"(b) : "l"(v));
}
__device__ __forceinline__ u64t fma2_(u64t a, u64t b, u64t c) {
    u64t d; asm("fma.rn.f32x2 %0, %1, %2, %3;" : "=l"(d) : "l"(a), "l"(b), "l"(c)); return d;
}

__device__ __forceinline__ uint32_t smem_u32(const void* p) {
    uint32_t a;
    asm("{ .reg .u64 t; cvta.to.shared.u64 t, %1; cvt.u32.u64 %0, t; }" : "=r"(a) : "l"(p));
    return a;
}
#define CP_ASYNC16(dst, src) \
    asm volatile("cp.async.ca.shared.global [%0], [%1], 16;" :: "r"(dst), "l"(src))
#define CP_COMMIT() asm volatile("cp.async.commit_group;" ::: "memory")
#define CP_WAIT1()  asm volatile("cp.async.wait_group 1;" ::: "memory")
#define CP_WAIT0()  asm volatile("cp.async.wait_group 0;" ::: "memory")

// ---------------------------------------------------------------------------
// split fp32 matrix -> bf16 hi/lo (vectorized by 4) -- used for adj/supports
// ---------------------------------------------------------------------------
__global__ void split_mat(const float* __restrict__ src, __nv_bfloat16* __restrict__ hi,
                          __nv_bfloat16* __restrict__ lo, int n4) {
    int i = blockIdx.x * 256 + threadIdx.x;
    if (i >= n4) return;
    float4 v = ((const float4*)src)[i];
    __nv_bfloat16 h0, h1, h2, h3, l0, l1, l2, l3;
    bf16split(v.x, h0, l0); bf16split(v.y, h1, l1);
    bf16split(v.z, h2, l2); bf16split(v.w, h3, l3);
    uint2 ph, pl;
    ph.x = (uint32_t)__bfloat16_as_ushort(h0) | ((uint32_t)__bfloat16_as_ushort(h1) << 16);
    ph.y = (uint32_t)__bfloat16_as_ushort(h2) | ((uint32_t)__bfloat16_as_ushort(h3) << 16);
    pl.x = (uint32_t)__bfloat16_as_ushort(l0) | ((uint32_t)__bfloat16_as_ushort(l1) << 16);
    pl.y = (uint32_t)__bfloat16_as_ushort(l2) | ((uint32_t)__bfloat16_as_ushort(l3) << 16);
    *(uint2*)&hi[(size_t)i * 4] = ph;
    *(uint2*)&lo[(size_t)i * 4] = pl;
}

// ---------------------------------------------------------------------------
// wmma bf16 split-precision GEMM (128x128 CTA, 64x32 warp tiles, cp.async
// double-buffered). C = Ah*Bh + Ah*Bl + Al*Bh in fp32.
// Grid mapping: bm = blockIdx.x (8 strips, fastest) so each wave shares B
// strips across the 8 bm CTAs via L2 and B is streamed from DRAM ~once.
// ---------------------------------------------------------------------------
#define GW_SMEM 75776

__global__ void __launch_bounds__(256)
gemm_wmma(const __nv_bfloat16* __restrict__ Ah, const __nv_bfloat16* __restrict__ Al,
          const __nv_bfloat16* __restrict__ Bh, const __nv_bfloat16* __restrict__ Bl,
          float* __restrict__ C, __nv_bfloat16* __restrict__ Chi,
          __nv_bfloat16* __restrict__ Clo, int Nc, float alpha) {
    extern __shared__ __align__(16) __nv_bfloat16 sm[];
    __nv_bfloat16* sAh = sm;
    __nv_bfloat16* sAl = sm + 10240;
    __nv_bfloat16* sBh = sm + 20480;
    __nv_bfloat16* sBl = sm + 29184;
    uint32_t uAh = smem_u32(sAh), uAl = smem_u32(sAl);
    uint32_t uBh = smem_u32(sBh), uBl = smem_u32(sBl);

    int tid = threadIdx.x;
    int wid = tid >> 5, lane = tid & 31;
    int bm = blockIdx.x * 128, bn = blockIdx.y * 128;
    int wm = (wid >> 2) * 64;
    int wn = (wid & 3) * 32;

    wmma::fragment<wmma::accumulator, 16, 16, 16, float> acc[4][2];
#pragma unroll
    for (int i = 0; i < 4; i++)
#pragma unroll
        for (int j = 0; j < 2; j++) wmma::fill_fragment(acc[i][j], 0.f);

    int ar = tid >> 1;
    int ac = (tid & 1) << 4;
    int br = tid >> 3;
    int bc = (tid & 7) << 4;

#define ISSUE(ch, s) do {                                                            \
    int _k0 = (ch) * 32;                                                             \
    const __nv_bfloat16* gA = Ah + (size_t)(bm + ar) * 1024 + _k0 + ac;              \
    const __nv_bfloat16* gAl2 = Al + (size_t)(bm + ar) * 1024 + _k0 + ac;            \
    uint32_t dA = uAh + (((s) * 128 + ar) * 40 + ac) * 2;                            \
    uint32_t dAl2 = uAl + (((s) * 128 + ar) * 40 + ac) * 2;                          \
    CP_ASYNC16(dA, gA); CP_ASYNC16(dA + 16, gA + 8);                                 \
    CP_ASYNC16(dAl2, gAl2); CP_ASYNC16(dAl2 + 16, gAl2 + 8);                         \
    const __nv_bfloat16* gB = Bh + (size_t)(_k0 + br) * Nc + bn + bc;                \
    const __nv_bfloat16* gBl2 = Bl + (size_t)(_k0 + br) * Nc + bn + bc;              \
    uint32_t dB = uBh + (((s) * 32 + br) * 136 + bc) * 2;                            \
    uint32_t dBl2 = uBl + (((s) * 32 + br) * 136 + bc) * 2;                          \
    CP_ASYNC16(dB, gB); CP_ASYNC16(dB + 16, gB + 8);                                 \
    CP_ASYNC16(dBl2, gBl2); CP_ASYNC16(dBl2 + 16, gBl2 + 8);                         \
} while (0)

    ISSUE(0, 0);
    CP_COMMIT();

    for (int ch = 0; ch < 32; ch++) {
        int s = ch & 1;
        if (ch + 1 < 32) {
            ISSUE(ch + 1, (ch + 1) & 1);
            CP_COMMIT();
            CP_WAIT1();
        } else {
            CP_WAIT0();
        }
        __syncthreads();

#pragma unroll
        for (int kk = 0; kk < 32; kk += 16) {
            wmma::fragment<wmma::matrix_a, 16, 16, 16, __nv_bfloat16, wmma::row_major> fah[4], fal[4];
            wmma::fragment<wmma::matrix_b, 16, 16, 16, __nv_bfloat16, wmma::row_major> fbh[2], fbl[2];
#pragma unroll
            for (int i = 0; i < 4; i++) {
                wmma::load_matrix_sync(fah[i], &sAh[(s * 128 + wm + i * 16) * 40 + kk], 40);
                wmma::load_matrix_sync(fal[i], &sAl[(s * 128 + wm + i * 16) * 40 + kk], 40);
            }
#pragma unroll
            for (int j = 0; j < 2; j++) {
                wmma::load_matrix_sync(fbh[j], &sBh[(s * 32 + kk) * 136 + wn + j * 16], 136);
                wmma::load_matrix_sync(fbl[j], &sBl[(s * 32 + kk) * 136 + wn + j * 16], 136);
            }
#pragma unroll
            for (int i = 0; i < 4; i++)
#pragma unroll
                for (int j = 0; j < 2; j++) {
                    wmma::mma_sync(acc[i][j], fah[i], fbh[j], acc[i][j]);
                    wmma::mma_sync(acc[i][j], fah[i], fbl[j], acc[i][j]);
                    wmma::mma_sync(acc[i][j], fal[i], fbh[j], acc[i][j]);
                }
        }
        __syncthreads();
    }
#undef ISSUE

    if (Chi == nullptr) {
#pragma unroll
        for (int i = 0; i < 4; i++)
#pragma unroll
            for (int j = 0; j < 2; j++) {
#pragma unroll
                for (int e = 0; e < 8; e++) acc[i][j].x[e] *= alpha;
                wmma::store_matrix_sync(&C[(size_t)(bm + wm + i * 16) * Nc + bn + wn + j * 16],
                                        acc[i][j], Nc, wmma::mem_row_major);
            }
    } else {
        float* stg = (float*)sm + wid * 336;
#pragma unroll
        for (int i = 0; i < 4; i++)
#pragma unroll
            for (int j = 0; j < 2; j++) {
#pragma unroll
                for (int e = 0; e < 8; e++) acc[i][j].x[e] *= alpha;
                wmma::store_matrix_sync(stg, acc[i][j], 20, wmma::mem_row_major);
                __syncwarp();
#pragma unroll
                for (int k = 0; k < 8; k++) {
                    int e = k * 32 + lane;
                    int r = e >> 4, cc = e & 15;
                    float v = stg[r * 20 + cc];
                    size_t gi = (size_t)(bm + wm + i * 16 + r) * Nc + bn + wn + j * 16 + cc;
                    C[gi] = v;
                    __nv_bfloat16 h, l;
                    bf16split(v, h, l);
                    Chi[gi] = h;
                    Clo[gi] = l;
                }
                __syncwarp();
            }
    }
}

// ---------------------------------------------------------------------------
// Weight repack
// ---------------------------------------------------------------------------
__global__ void repack_weights(const float* __restrict__ W_de, const float* __restrict__ Wq_t,
                               const float* __restrict__ W_1,  const float* __restrict__ Wk_t,
                               const float* __restrict__ Wv_t, const float* __restrict__ W_c1,
                               const float* __restrict__ Wq_s, const float* __restrict__ Wk_s,
                               const float* __restrict__ Wv_s, const float* __restrict__ W_g) {
    int idx = blockIdx.x * 256 + threadIdx.x;
    if (idx < 2048) {
        int i = idx >> 6, o = idx & 63;
        g_WT[WT_DQ1 + idx * 4 + 0] = W_de[o * 32 + i];
        g_WT[WT_DQ1 + idx * 4 + 1] = Wq_t[o * 32 + i];
        g_WT[WT_DQ1 + idx * 4 + 2] = W_1[o * 32 + i];
        g_WT[WT_DQ1 + idx * 4 + 3] = 0.f;
    }
    if (idx < 4096) {
        int i = idx >> 6, c = idx & 63;
        g_WT[WT_KVT + idx * 2 + 0] = Wk_t[c * 64 + i];
        g_WT[WT_KVT + idx * 2 + 1] = Wv_t[c * 64 + i];
        g_WT[WT_KVS + idx * 2 + 0] = Wk_s[c * 64 + i];
        g_WT[WT_KVS + idx * 2 + 1] = Wv_s[c * 64 + i];
        g_WT[WT_QS + idx] = Wq_s[c * 64 + i];
        g_WT[WT_C1 + idx * 4 + 0] = W_c1[(c * 64 + i) * 3 + 0];
        g_WT[WT_C1 + idx * 4 + 1] = W_c1[(c * 64 + i) * 3 + 1];
        g_WT[WT_C1 + idx * 4 + 2] = W_c1[(c * 64 + i) * 3 + 2];
        g_WT[WT_C1 + idx * 4 + 3] = 0.f;
    }
    if (idx < 12288) {
        int j = idx >> 6, o = idx & 63;
        g_WT[WT_G + idx * 2 + 0] = W_g[o * 192 + j];
        g_WT[WT_G + idx * 2 + 1] = W_g[(o + 64) * 192 + j];
    }
}

// ---------------------------------------------------------------------------
// Precompute: delay(n,t), M = CS @ W_mii^T
// ---------------------------------------------------------------------------
__global__ void precompute_kernel(const float* __restrict__ CD,
                                  const float* __restrict__ Wd,
                                  const float* __restrict__ CS,
                                  const float* __restrict__ W_mii) {
    int idx = blockIdx.x * 256 + threadIdx.x;
    if (idx < NT) {
        int n = idx / TT, t = idx - n * TT;
        float a = 0.f;
#pragma unroll
        for (int d = 0; d < 16; d++) a = fmaf(CD[n * 16 + d], Wd[d * TT + t], a);
        g_delay[idx] = sigmoidf_(tanhf(a));
    }
    if (idx < NNODE * COUT) {
        int n = idx / COUT, o = idx - n * COUT;
        float a = 0.f;
#pragma unroll
        for (int e = 0; e < 16; e++) a = fmaf(CS[n * 16 + e], W_mii[o * 16 + e], a);
        g_M[idx] = a;
    }
}

__global__ void rowsum_kernel(const float* __restrict__ adj) {
    __shared__ float red[256];
    int n = blockIdx.x;
    float s = 0.f;
    for (int m = threadIdx.x; m < NNODE; m += 256) s += adj[(size_t)n * NNODE + m];
    red[threadIdx.x] = s;
    __syncthreads();
    for (int w = 128; w > 0; w >>= 1) {
        if (threadIdx.x < w) red[threadIdx.x] += red[threadIdx.x + w];
        __syncthreads();
    }
    if (threadIdx.x == 0) g_rowsum[n] = red[0];
}

// ---------------------------------------------------------------------------
// u + Ubig: writes Ubig directly as bf16 hi/lo (GEMM B operand)
// ---------------------------------------------------------------------------
__global__ void u_kernel(const float* __restrict__ x, const float* __restrict__ W_pro,
                         const float* __restrict__ b_pro, const float* __restrict__ CS) {
    int b = blockIdx.y;
    int j = blockIdx.x * 256 + threadIdx.x;
    float u = __ldg(&b_pro[0]);
#pragma unroll 8
    for (int i = 0; i < 32; i++)
        u = fmaf(__ldg(&W_pro[i]), x[((size_t)(b * 32 + i)) * NT + j], u);
    g_u[(size_t)b * NT + j] = u;
    int n = j / TT, t = j - n * TT;
#pragma unroll
    for (int e = 0; e < 16; e++) {
        float v = __ldg(&CS[n * 16 + e]) * u;
        size_t idx = (size_t)n * EB + e * (BB * TT) + b * TT + t;
        __nv_bfloat16 h, l;
        bf16split(v, h, l);
        g_Bh[idx] = h;
        g_Bl[idx] = l;
    }
}

// ---------------------------------------------------------------------------
// MEGA kernel: all heavy loops on the f32x2 (FFMA2) pipe.
// ---------------------------------------------------------------------------
__global__ void __launch_bounds__(256) mega_kernel(
    const float* __restrict__ x, const float* __restrict__ W_mii,
    const float* __restrict__ b_mii,
    const float* __restrict__ b_de, const float* __restrict__ bq_t,
    const float* __restrict__ b_1,  const float* __restrict__ bk_t,
    const float* __restrict__ bv_t, const float* __restrict__ b_c1,
    const float* __restrict__ bq_s, const float* __restrict__ bk_s,
    const float* __restrict__ bv_s) {
    __shared__ float xs[32][26];
    __shared__ float sD[64][26];
    __shared__ float sQ[64][26];
    __shared__ float sK[64][26];
    __shared__ float sV[64][26];
    __shared__ float sX1[64][26];
    __shared__ float sA[24][26];
    __shared__ float sZ[16][24];
    __shared__ float su[24], sdel[24], sM[64];
    __shared__ float sWm[64][16];

    int b = blockIdx.y, n = blockIdx.x, tid = threadIdx.x;
    int o = tid >> 2, q = tid & 3;
    int tb = q * 6;

    for (int p = tid; p < 768; p += 256) {
        int i = p / 24, t = p - i * 24;
        xs[i][t] = x[((size_t)(b * 32 + i) * NNODE + n) * TT + t];
    }
    for (int p = tid; p < 384; p += 256) {
        int e = p / 24, t = p - e * 24;
        sZ[e][t] = g_Z[(size_t)n * EB + e * (BB * TT) + b * TT + t];
    }
    for (int p = tid; p < 1024; p += 256) sWm[p >> 4][p & 15] = W_mii[p];
    if (tid < 24) {
        su[tid] = g_u[(size_t)b * NT + n * TT + tid];
        sdel[tid] = g_delay[n * TT + tid];
    }
    if (tid < 64) sM[tid] = g_M[n * 64 + tid];
    __syncthreads();

    // ---- D(*delay), Qt, xin1 ----
    {
        u64t aD[3], aQ[3], aX[3];
        float bd = __ldg(&b_de[o]), bq = __ldg(&bq_t[o]), bx = __ldg(&b_1[o]);
#pragma unroll
        for (int j = 0; j < 3; j++) { aD[j] = pk2(bd, bd); aQ[j] = pk2(bq, bq); aX[j] = pk2(bx, bx); }
#pragma unroll 4
        for (int i = 0; i < 32; i++) {
            float4 w = *(const float4*)&g_WT[WT_DQ1 + (i * 64 + o) * 4];
            u64t wx = pk2(w.x, w.x), wy = pk2(w.y, w.y), wz = pk2(w.z, w.z);
#pragma unroll
            for (int j = 0; j < 3; j++) {
                u64t X = pk2v(*(const float2*)&xs[i][tb + 2 * j]);
                aD[j] = fma2_(wx, X, aD[j]);
                aQ[j] = fma2_(wy, X, aQ[j]);
                aX[j] = fma2_(wz, X, aX[j]);
            }
        }
        size_t gb = (((size_t)b * 64 + o) * NNODE + n) * TT;
#pragma unroll
        for (int j = 0; j < 3; j++) {
            int t0 = tb + 2 * j;
            float d0, d1, q0, q1, x0, x1;
            upk2(aD[j], d0, d1); upk2(aQ[j], q0, q1); upk2(aX[j], x0, x1);
            sD[o][t0] = d0 * sdel[t0]; sD[o][t0 + 1] = d1 * sdel[t0 + 1];
            sQ[o][t0] = q0; sQ[o][t0 + 1] = q1;
            sX1[o][t0] = x0; sX1[o][t0 + 1] = x1;
            *(float2*)&g_xin1[gb + t0] = make_float2(x0, x1);
        }
    }
    __syncthreads();

    // ---- Kt,Vt = conv1x1(D) ----
    {
        u64t ak[3], av[3];
        float bk0 = __ldg(&bk_t[o]), bv0 = __ldg(&bv_t[o]);
#pragma unroll
        for (int j = 0; j < 3; j++) { ak[j] = pk2(bk0, bk0); av[j] = pk2(bv0, bv0); }
#pragma unroll 4
        for (int i = 0; i < 64; i++) {
            float2 w = *(const float2*)&g_WT[WT_KVT + (i * 64 + o) * 2];
            u64t wk = pk2(w.x, w.x), wv = pk2(w.y, w.y);
#pragma unroll
            for (int j = 0; j < 3; j++) {
                u64t D = pk2v(*(const float2*)&sD[i][tb + 2 * j]);
                ak[j] = fma2_(wk, D, ak[j]);
                av[j] = fma2_(wv, D, av[j]);
            }
        }
#pragma unroll
        for (int j = 0; j < 3; j++) {
            int t0 = tb + 2 * j;
            float k0, k1, v0, v1;
            upk2(ak[j], k0, k1); upk2(av[j], v0, v1);
            sK[o][t0] = k0; sK[o][t0 + 1] = k1;
            sV[o][t0] = v0; sV[o][t0 + 1] = v1;
        }
    }
    __syncthreads();

    // ---- scores (s-pairs on FFMA2) ----
    for (int p = tid; p < 288; p += 256) {
        int t = p / 12, sp = (p - t * 12) * 2;
        u64t acc2 = pk2(0.f, 0.f);
#pragma unroll 8
        for (int c = 0; c < 64; c++) {
            float qv = sQ[c][t];
            acc2 = fma2_(pk2(qv, qv), pk2v(*(const float2*)&sK[c][sp]), acc2);
        }
        float a0, a1;
        upk2(acc2, a0, a1);
        sA[t][sp] = a0 * 0.125f;
        sA[t][sp + 1] = a1 * 0.125f;
    }
    __syncthreads();
    if (tid < 24) {
        float mx = -1e30f;
        for (int s = 0; s < 24; s++) mx = fmaxf(mx, sA[tid][s]);
        float sum = 0.f;
        for (int s = 0; s < 24; s++) { float e = __expf(sA[tid][s] - mx); sA[tid][s] = e; sum += e; }
        float inv = 1.f / sum;
        for (int s = 0; s < 24; s++) sA[tid][s] *= inv;
    }
    __syncthreads();

    // ---- XD = A@V + xin1 (s-pairs on FFMA2) ----
    for (int p = tid; p < 1536; p += 256) {
        int c = p / 24, t = p - c * 24;
        u64t acc2 = pk2(0.f, 0.f);
#pragma unroll
        for (int s = 0; s < 24; s += 2)
            acc2 = fma2_(pk2v(*(const float2*)&sA[t][s]),
                         pk2v(*(const float2*)&sV[c][s]), acc2);
        float a0, a1;
        upk2(acc2, a0, a1);
        sX1[c][t] += a0 + a1;
    }
    __syncthreads();

    // ---- temporal conv (k=3, pad 1): sX1 -> sD ----
    {
        u64t A[3];
        float bo = __ldg(&b_c1[o]);
#pragma unroll
        for (int j = 0; j < 3; j++) A[j] = pk2(bo, bo);
#pragma unroll 4
        for (int i = 0; i < 64; i++) {
            float4 w = *(const float4*)&g_WT[WT_C1 + (i * 64 + o) * 4];
            u64t w0 = pk2(w.x, w.x), w1 = pk2(w.y, w.y), w2 = pk2(w.z, w.z);
#pragma unroll
            for (int j = 0; j < 3; j++) {
                int t0 = tb + 2 * j;
                float2 v0 = *(const float2*)&sX1[i][t0];
                float xm = (t0 > 0) ? sX1[i][t0 - 1] : 0.f;
                float xp = (t0 < 22) ? sX1[i][t0 + 2] : 0.f;
                A[j] = fma2_(w0, pk2(xm, v0.x), A[j]);
                A[j] = fma2_(w1, pk2(v0.x, v0.y), A[j]);
                A[j] = fma2_(w2, pk2(v0.y, xp), A[j]);
            }
        }
#pragma unroll
        for (int j = 0; j < 3; j++) {
            int t0 = tb + 2 * j;
            float a0, a1;
            upk2(A[j], a0, a1);
            sD[o][t0] = a0; sD[o][t0 + 1] = a1;
        }
    }
    __syncthreads();

    // ---- Qs = conv1x1(x1) -> sQ ----
    {
        u64t A[3];
        float bqc = __ldg(&bq_s[o]);
#pragma unroll
        for (int j = 0; j < 3; j++) A[j] = pk2(bqc, bqc);
#pragma unroll 4
        for (int i = 0; i < 64; i++) {
            float w = __ldg(&g_WT[WT_QS + i * 64 + o]);
            u64t ww = pk2(w, w);
#pragma unroll
            for (int j = 0; j < 3; j++)
                A[j] = fma2_(ww, pk2v(*(const float2*)&sD[i][tb + 2 * j]), A[j]);
        }
#pragma unroll
        for (int j = 0; j < 3; j++) {
            int t0 = tb + 2 * j;
            float a0, a1;
            upk2(A[j], a0, a1);
            sQ[o][t0] = a0; sQ[o][t0 + 1] = a1;
        }
    }
    // ---- S (rank-16 recon, t-pairs on FFMA2) -> sV ----
    {
        float rs1 = 1.f + g_rowsum[n];
        for (int p = tid; p < 768; p += 256) {
            int c = p / 12, tp = (p - c * 12) * 2;
            float base = __ldg(&b_mii[c]) * rs1;
            float mc = sM[c];
            u64t a2 = pk2(fmaf(su[tp], mc, base), fmaf(su[tp + 1], mc, base));
#pragma unroll
            for (int e = 0; e < 16; e++) {
                float w = sWm[c][e];
                a2 = fma2_(pk2(w, w), pk2v(*(const float2*)&sZ[e][tp]), a2);
            }
            float a0, a1;
            upk2(a2, a0, a1);
            sV[c][tp] = a0; sV[c][tp + 1] = a1;
        }
    }
    __syncthreads();

    // ---- Ks,Vs = conv1x1(S): sV -> sK, sX1 ----
    {
        u64t ak[3], av[3];
        float bk0 = __ldg(&bk_s[o]), bv0 = __ldg(&bv_s[o]);
#pragma unroll
        for (int j = 0; j < 3; j++) { ak[j] = pk2(bk0, bk0); av[j] = pk2(bv0, bv0); }
#pragma unroll 4
        for (int i = 0; i < 64; i++) {
            float2 w = *(const float2*)&g_WT[WT_KVS + (i * 64 + o) * 2];
            u64t wk = pk2(w.x, w.x), wv = pk2(w.y, w.y);
#pragma unroll
            for (int j = 0; j < 3; j++) {
                u64t D = pk2v(*(const float2*)&sV[i][tb + 2 * j]);
                ak[j] = fma2_(wk, D, ak[j]);
                av[j] = fma2_(wv, D, av[j]);
            }
        }
#pragma unroll
        for (int j = 0; j < 3; j++) {
            int t0 = tb + 2 * j;
            float k0, k1, v0, v1;
            upk2(ak[j], k0, k1); upk2(av[j], v0, v1);
            sK[o][t0] = k0; sK[o][t0 + 1] = k1;
            sX1[o][t0] = v0; sX1[o][t0 + 1] = v1;
        }
    }
    __syncthreads();

    // ---- scores (spatial, s-pairs) ----
    for (int p = tid; p < 288; p += 256) {
        int t = p / 12, sp = (p - t * 12) * 2;
        u64t acc2 = pk2(0.f, 0.f);
#pragma unroll 8
        for (int c = 0; c < 64; c++) {
            float qv = sQ[c][t];
            acc2 = fma2_(pk2(qv, qv), pk2v(*(const float2*)&sK[c][sp]), acc2);
        }
        float a0, a1;
        upk2(acc2, a0, a1);
        sA[t][sp] = a0 * 0.125f;
        sA[t][sp + 1] = a1 * 0.125f;
    }
    __syncthreads();
    if (tid < 24) {
        float mx = -1e30f;
        for (int s = 0; s < 24; s++) mx = fmaxf(mx, sA[tid][s]);
        float sum = 0.f;
        for (int s = 0; s < 24; s++) { float e = __expf(sA[tid][s] - mx); sA[tid][s] = e; sum += e; }
        float inv = 1.f / sum;
        for (int s = 0; s < 24; s++) sA[tid][s] *= inv;
    }
    __syncthreads();

    // ---- XS = A@V (s-pairs) -> packed + bf16 split ----
    for (int p = tid; p < 1536; p += 256) {
        int c = p / 24, t = p - c * 24;
        u64t acc2 = pk2(0.f, 0.f);
#pragma unroll
        for (int s = 0; s < 24; s += 2)
            acc2 = fma2_(pk2v(*(const float2*)&sA[t][s]),
                         pk2v(*(const float2*)&sX1[c][s]), acc2);
        float a0, a1;
        upk2(acc2, a0, a1);
        float acc = a0 + a1;
        size_t gi = (size_t)n * JCOLS + (b * 64 + c) * 24 + t;
        g_XSp[gi] = acc;
        __nv_bfloat16 h, l;
        bf16split(acc, h, l);
        g_Bh[gi] = h;
        g_Bl[gi] = l;
    }
}

// ---------------------------------------------------------------------------
// Combine: f32x2 inner loop, per-thread t = 6q..6q+5.
// ---------------------------------------------------------------------------
__global__ void __launch_bounds__(256) combine_kernel(const float* __restrict__ bg,
                                                      float* __restrict__ out) {
    __shared__ float xs[64][26];
    __shared__ float y1[64][26];
    __shared__ float y2[64][26];
    int b = blockIdx.y, n = blockIdx.x, tid = threadIdx.x;
    size_t row = (size_t)n * JCOLS;
    int cb = b * 64 * 24;

    for (int p = tid; p < 1536; p += 256) {
        int c = p / 24, t = p - c * 24;
        size_t g = row + cb + c * 24 + t;
        float a = g_XSp[g];
        xs[c][t] = a;
        y1[c][t] = g_Y1p[g];
        y2[c][t] = g_Y2r[g] - a;
    }
    __syncthreads();

    int o = tid & 63, q = tid >> 6;
    int tb = q * 6;
    u64t F[3], G[3];
    float bf = __ldg(&bg[o]), bgt = __ldg(&bg[o + 64]);
#pragma unroll
    for (int j = 0; j < 3; j++) { F[j] = pk2(bf, bf); G[j] = pk2(bgt, bgt); }
#pragma unroll 2
    for (int c = 0; c < 64; c++) {
        float2 w0 = *(const float2*)&g_WT[WT_G + ((3 * c + 0) * 64 + o) * 2];
        float2 w1 = *(const float2*)&g_WT[WT_G + ((3 * c + 1) * 64 + o) * 2];
        float2 w2 = *(const float2*)&g_WT[WT_G + ((3 * c + 2) * 64 + o) * 2];
        u64t w0f = pk2(w0.x, w0.x), w0g = pk2(w0.y, w0.y);
        u64t w1f = pk2(w1.x, w1.x), w1g = pk2(w1.y, w1.y);
        u64t w2f = pk2(w2.x, w2.x), w2g = pk2(w2.y, w2.y);
#pragma unroll
        for (int j = 0; j < 3; j++) {
            u64t A  = pk2v(*(const float2*)&xs[c][tb + 2 * j]);
            u64t B1 = pk2v(*(const float2*)&y1[c][tb + 2 * j]);
            u64t B2 = pk2v(*(const float2*)&y2[c][tb + 2 * j]);
            F[j] = fma2_(w0f, A, F[j]);
            F[j] = fma2_(w1f, B1, F[j]);
            F[j] = fma2_(w2f, B2, F[j]);
            G[j] = fma2_(w0g, A, G[j]);
            G[j] = fma2_(w1g, B1, G[j]);
            G[j] = fma2_(w2g, B2, G[j]);
        }
    }
    size_t obase = (((size_t)b * 64 + o) * NNODE + n) * TT;
#pragma unroll
    for (int j = 0; j < 3; j++) {
        int t0 = tb + 2 * j;
        float f0, f1, g0, g1;
        upk2(F[j], f0, f1); upk2(G[j], g0, g1);
        float2 xi = *(const float2*)&g_xin1[obase + t0];
        float2 ov;
        ov.x = (f0 + xi.x) * sigmoidf_(g0);
        ov.y = (f1 + xi.y) * sigmoidf_(g1);
        *(float2*)&out[obase + t0] = ov;
    }
}

// ---------------------------------------------------------------------------
// Host launcher
// ---------------------------------------------------------------------------
extern "C" void kernel_launch(void* const* d_in, const int* in_sizes, int n_in,
                              void* d_out, int out_size) {
    const float* x        = (const float*)d_in[0];
    const float* supports = (const float*)d_in[1];
    const float* CD       = (const float*)d_in[2];
    const float* CS       = (const float*)d_in[3];
    const float* adj      = (const float*)d_in[4];
    const float* W_de     = (const float*)d_in[5];
    const float* b_de     = (const float*)d_in[6];
    const float* Wd       = (const float*)d_in[7];
    const float* W_pro    = (const float*)d_in[8];
    const float* b_pro    = (const float*)d_in[9];
    const float* W_mii    = (const float*)d_in[10];
    const float* b_mii    = (const float*)d_in[11];
    const float* W_1      = (const float*)d_in[12];
    const float* b_1      = (const float*)d_in[13];
    const float* Wq_t     = (const float*)d_in[14];
    const float* bq_t     = (const float*)d_in[15];
    const float* Wk_t     = (const float*)d_in[16];
    const float* bk_t     = (const float*)d_in[17];
    const float* Wv_t     = (const float*)d_in[18];
    const float* bv_t     = (const float*)d_in[19];
    const float* W_c1     = (const float*)d_in[20];
    const float* b_c1     = (const float*)d_in[21];
    const float* Wq_s     = (const float*)d_in[22];
    const float* bq_s     = (const float*)d_in[23];
    const float* Wk_s     = (const float*)d_in[24];
    const float* bk_s     = (const float*)d_in[25];
    const float* Wv_s     = (const float*)d_in[26];
    const float* bv_s     = (const float*)d_in[27];
    const float* W_g      = (const float*)d_in[28];
    const float* b_g      = (const float*)d_in[29];
    float* out = (float*)d_out;

    float *p_Z, *p_XSp, *p_Y1p, *p_Y2r;
    __nv_bfloat16 *p_Ah, *p_Al, *p_Bh, *p_Bl, *p_Ch, *p_Cl;
    cudaGetSymbolAddress((void**)&p_Z,   g_Z);
    cudaGetSymbolAddress((void**)&p_XSp, g_XSp);
    cudaGetSymbolAddress((void**)&p_Y1p, g_Y1p);
    cudaGetSymbolAddress((void**)&p_Y2r, g_Y2r);
    cudaGetSymbolAddress((void**)&p_Ah,  g_Ah);
    cudaGetSymbolAddress((void**)&p_Al,  g_Al);
    cudaGetSymbolAddress((void**)&p_Bh,  g_Bh);
    cudaGetSymbolAddress((void**)&p_Bl,  g_Bl);
    cudaGetSymbolAddress((void**)&p_Ch,  g_Ch);
    cudaGetSymbolAddress((void**)&p_Cl,  g_Cl);

    cudaFuncSetAttribute(gemm_wmma, cudaFuncAttributeMaxDynamicSharedMemorySize, GW_SMEM);

    // weight repack + small precompute
    repack_weights<<<48, 256>>>(W_de, Wq_t, W_1, Wk_t, Wv_t, W_c1,
                                Wq_s, Wk_s, Wv_s, W_g);
    precompute_kernel<<<256, 256>>>(CD, Wd, CS, W_mii);
    rowsum_kernel<<<NNODE, 256>>>(adj);

    // Z = adj @ Ubig  (u_kernel writes Ubig split directly)
    split_mat<<<(NNODE * NNODE / 4 + 255) / 256, 256>>>(adj, p_Ah, p_Al, NNODE * NNODE / 4);
    u_kernel<<<dim3(NT / 256, BB), 256>>>(x, W_pro, b_pro, CS);
    gemm_wmma<<<dim3(8, EB / 128), 256, GW_SMEM>>>(p_Ah, p_Al, p_Bh, p_Bl, p_Z,
                                                   nullptr, nullptr, EB, 1.f);

    // fused block -> XS packed (fp32 + bf16 split)
    split_mat<<<(NNODE * NNODE / 4 + 255) / 256, 256>>>(supports, p_Ah, p_Al, NNODE * NNODE / 4);
    mega_kernel<<<dim3(NNODE, BB), 256>>>(x, W_mii, b_mii, b_de, bq_t, b_1,
                                          bk_t, bv_t, b_c1, bq_s, bk_s, bv_s);

    // cheby: Y1 = S@XS (fused split epilogue) ; Y2r = 2*S@Y1
    gemm_wmma<<<dim3(8, JCOLS / 128), 256, GW_SMEM>>>(p_Ah, p_Al, p_Bh, p_Bl, p_Y1p,
                                                      p_Ch, p_Cl, JCOLS, 1.f);
    gemm_wmma<<<dim3(8, JCOLS / 128), 256, GW_SMEM>>>(p_Ah, p_Al, p_Ch, p_Cl, p_Y2r,
                                                      nullptr, nullptr, JCOLS, 2.f);

    // W_g epilogue + residual + gate
    combine_kernel<<<dim3(NNODE, BB), 256>>>(b_g, out);

    (void)in_sizes; (void)n_in; (void)out_size;
}